// round 1
// baseline (speedup 1.0000x reference)
#include <cuda_runtime.h>
#include <math.h>

#define B_ 2
#define L_ 2048
#define H_ 2048
#define K_ 128
#define BL_ (B_*L_)
#define NT_ (L_/64)
#define SCALE_ 0.08838834764831845f
#define EPS_ 1e-5f

// ---------------- scratch (static device allocations) ----------------
__device__ float g_q[BL_*K_];          // silu(q)*scale        2 MB
__device__ float g_k[BL_*K_];          // sigmoid(k)           2 MB
__device__ float g_D[BL_*K_];          // decay = sigmoid(-k)  2 MB
__device__ float g_A[B_*NT_*128*64];   // banded scores, dense 2 MB
__device__ float g_o[BL_*H_];          // GLA output          32 MB
__device__ float g_go[BL_*H_];         // output gate         32 MB

__device__ __forceinline__ float sigmoid_f(float v) { return 1.f/(1.f+expf(-v)); }

// ============ 1) q/k projection GEMM: [4096 x 2048] @ [128 x 2048]^T x2 ============
// grid: (4, 64) ; tile 64x64, BK=16, 256 thr, 4x4 per thread
__global__ void proj_kernel(const float* __restrict__ x,
                            const float* __restrict__ Wq,
                            const float* __restrict__ Wk) {
    __shared__ float sX[16][64];
    __shared__ float sW[16][64];
    const int m0 = blockIdx.y * 64;
    const int n0 = blockIdx.x * 64;            // 0..255 : [0,128)=q, [128,256)=k
    const bool is_q = (n0 < 128);
    const float* W = is_q ? Wq : Wk;
    const int j0 = is_q ? n0 : (n0 - 128);
    const int tid = threadIdx.x;
    const int tx = tid & 15, ty = tid >> 4;
    const int lr = tid >> 2, lc = tid & 3;

    float acc[4][4];
    #pragma unroll
    for (int i = 0; i < 4; ++i)
        #pragma unroll
        for (int j = 0; j < 4; ++j) acc[i][j] = 0.f;

    const float* xrow = x + (size_t)(m0 + lr) * H_ + lc * 4;
    const float* wrow = W + (size_t)(j0 + lr) * H_ + lc * 4;

    for (int k0 = 0; k0 < H_; k0 += 16) {
        float4 xa = *reinterpret_cast<const float4*>(xrow + k0);
        float4 wa = *reinterpret_cast<const float4*>(wrow + k0);
        __syncthreads();
        sX[lc*4+0][lr] = xa.x; sX[lc*4+1][lr] = xa.y;
        sX[lc*4+2][lr] = xa.z; sX[lc*4+3][lr] = xa.w;
        sW[lc*4+0][lr] = wa.x; sW[lc*4+1][lr] = wa.y;
        sW[lc*4+2][lr] = wa.z; sW[lc*4+3][lr] = wa.w;
        __syncthreads();
        #pragma unroll
        for (int kk = 0; kk < 16; ++kk) {
            float4 a4 = *reinterpret_cast<float4*>(&sX[kk][ty*4]);
            float4 b4 = *reinterpret_cast<float4*>(&sW[kk][tx*4]);
            float a[4] = {a4.x, a4.y, a4.z, a4.w};
            float b[4] = {b4.x, b4.y, b4.z, b4.w};
            #pragma unroll
            for (int i = 0; i < 4; ++i)
                #pragma unroll
                for (int j = 0; j < 4; ++j)
                    acc[i][j] += a[i] * b[j];
        }
    }

    #pragma unroll
    for (int i = 0; i < 4; ++i) {
        int row = m0 + ty*4 + i;
        #pragma unroll
        for (int j = 0; j < 4; ++j) {
            int col = j0 + tx*4 + j;   // local column within [0,128)
            float v = acc[i][j];
            if (is_q) {
                g_q[row*K_ + col] = v * sigmoid_f(v) * SCALE_;
            } else {
                float ks = sigmoid_f(v);
                g_k[row*K_ + col] = ks;
                g_D[row*K_ + col] = 1.f / (1.f + expf(ks));   // = sigmoid(-ks) = exp(g)
            }
        }
    }
}

// ============ 2) banded score matrix A[t,s], window 64, via cumprods ============
// grid: (NT_, B_), 256 threads. Per block: t-tile of 64, 4 sub-blocks of 16.
__global__ void gla_A_kernel() {
    const int tt = blockIdx.x, b = blockIdx.y;
    const int T0 = tt * 64;
    const int base = b * L_;
    const int tid = threadIdx.x;

    // skT[k][si]: k-tilde transposed (s window of 79, padded to 80)
    __shared__ float skT[128][80];   // 40 KB
    __shared__ float sqT[128][16];   //  8 KB

    float* At = &g_A[(size_t)(b * NT_ + tt) * 128 * 64];
    // zero-fill dense tile (later valid writes ordered by __syncthreads)
    for (int idx = tid; idx < 128 * 64; idx += 256) At[idx] = 0.f;

    for (int sub = 0; sub < 4; ++sub) {
        const int Ti = T0 + sub * 16;
        __syncthreads();
        // load raw k for s in [Ti-63, Ti+15]  (79 values)
        for (int idx = tid; idx < 79 * 128; idx += 256) {
            int si = idx >> 7;
            int k  = idx & 127;
            int s  = Ti - 63 + si;
            skT[k][si] = (s >= 0) ? g_k[(base + s) * K_ + k] : 0.f;
        }
        __syncthreads();
        if (tid < 128) {
            // backward scan: k~[s] = k[s] * prod_{u=s+1..Ti} D[u]   (s < Ti)
            int k = tid;
            float p = 1.f;
            for (int si = 62; si >= 0; --si) {
                int u = Ti - 62 + si;            // = s+1
                float d = (u >= 0) ? g_D[(base + u) * K_ + k] : 1.f;
                p *= d;
                skT[k][si] *= p;
            }
        } else {
            // forward scan: a[t] = prod_{u=Ti+1..t} D[u]
            // q~[t] = q[t]*a[t] ; k~[s] = k[s]/a[s] for s in (Ti, Ti+15]
            int k = tid - 128;
            sqT[k][0] = g_q[(base + Ti) * K_ + k];
            float ap = 1.f;
            #pragma unroll
            for (int j = 1; j < 16; ++j) {
                int u = Ti + j;
                ap *= g_D[(base + u) * K_ + k];
                sqT[k][j] = g_q[(base + u) * K_ + k] * ap;
                skT[k][63 + j] *= (1.f / ap);
            }
        }
        __syncthreads();
        // dot phase: pairs (t_i in [0,16), s_i in [0,79)); valid iff t_i <= s_i <= t_i+63
        for (int r = 0; r < 5; ++r) {
            int p  = r * 256 + tid;              // 1280 slots (16 x 80)
            int ti = p / 80;
            int si = p - ti * 80;
            if (si < 79 && si >= ti && si <= ti + 63) {
                float acc = 0.f;
                #pragma unroll 16
                for (int k = 0; k < 128; ++k)
                    acc += sqT[k][ti] * skT[k][si];
                int sidx = sub * 16 + 1 + si;    // position within 128-s-span of tile
                At[sidx * 64 + sub * 16 + ti] = acc;
            }
        }
    }
}

// ============ 3) o = A_band @ X : per block 64(t) x 64(v), K = 128(s) ============
// grid: (H/64, NT_, B_)
__global__ void gla_o_kernel(const float* __restrict__ x) {
    const int vt = blockIdx.x, tt = blockIdx.y, b = blockIdx.z;
    const int T0 = tt * 64, v0 = vt * 64;
    const float* At = &g_A[(size_t)(b * NT_ + tt) * 128 * 64];

    __shared__ float sA[16][64];
    __shared__ float sV[16][64];
    const int tid = threadIdx.x;
    const int tx = tid & 15, ty = tid >> 4;

    float acc[4][4];
    #pragma unroll
    for (int i = 0; i < 4; ++i)
        #pragma unroll
        for (int j = 0; j < 4; ++j) acc[i][j] = 0.f;

    for (int ks = 0; ks < 8; ++ks) {
        __syncthreads();
        #pragma unroll
        for (int s4 = 0; s4 < 4; ++s4) {
            int id = tid + s4 * 256;
            int kk = id >> 6, c = id & 63;
            sA[kk][c] = At[(ks * 16 + kk) * 64 + c];
        }
        #pragma unroll
        for (int s4 = 0; s4 < 4; ++s4) {
            int id = tid + s4 * 256;
            int kk = id >> 6, c = id & 63;
            int s = T0 - 64 + ks * 16 + kk;
            sV[kk][c] = (s >= 0) ? x[((size_t)(b * L_ + s)) * H_ + v0 + c] : 0.f;
        }
        __syncthreads();
        #pragma unroll
        for (int kk = 0; kk < 16; ++kk) {
            float4 a4 = *reinterpret_cast<float4*>(&sA[kk][ty*4]);
            float4 v4 = *reinterpret_cast<float4*>(&sV[kk][tx*4]);
            float a[4] = {a4.x, a4.y, a4.z, a4.w};
            float v[4] = {v4.x, v4.y, v4.z, v4.w};
            #pragma unroll
            for (int i = 0; i < 4; ++i)
                #pragma unroll
                for (int j = 0; j < 4; ++j)
                    acc[i][j] += a[i] * v[j];
        }
    }
    #pragma unroll
    for (int i = 0; i < 4; ++i)
        #pragma unroll
        for (int j = 0; j < 4; ++j)
            g_o[((size_t)(b * L_ + T0 + ty*4 + i)) * H_ + v0 + tx*4 + j] = acc[i][j];
}

// ============ 4) go = o @ Wog^T + x @ Wig^T : M=4096 N=2048 K=4096 ============
// grid: (16, 32), tile 128x128, BK=16, 256 thr, 8x8 per thread
__global__ void gemm_go_kernel(const float* __restrict__ x,
                               const float* __restrict__ Wog,
                               const float* __restrict__ Wig) {
    __shared__ float sA[16][128];
    __shared__ float sB[16][128];
    const int m0 = blockIdx.y * 128;
    const int n0 = blockIdx.x * 128;
    const int tid = threadIdx.x;
    const int tx = tid & 15, ty = tid >> 4;

    float acc[8][8];
    #pragma unroll
    for (int i = 0; i < 8; ++i)
        #pragma unroll
        for (int j = 0; j < 8; ++j) acc[i][j] = 0.f;

    for (int k0 = 0; k0 < 2 * H_; k0 += 16) {
        const float* Asrc; const float* Bsrc; int kb;
        if (k0 < H_) { Asrc = g_o; Bsrc = Wog; kb = k0; }
        else         { Asrc = x;   Bsrc = Wig; kb = k0 - H_; }
        __syncthreads();
        #pragma unroll
        for (int s = 0; s < 2; ++s) {
            int id = tid + s * 256;          // 512 float4 slots
            int row = id >> 2, fc = id & 3;
            float4 a = *reinterpret_cast<const float4*>(&Asrc[(size_t)(m0 + row) * H_ + kb + fc * 4]);
            float4 bb = *reinterpret_cast<const float4*>(&Bsrc[(size_t)(n0 + row) * H_ + kb + fc * 4]);
            sA[fc*4+0][row] = a.x;  sA[fc*4+1][row] = a.y;
            sA[fc*4+2][row] = a.z;  sA[fc*4+3][row] = a.w;
            sB[fc*4+0][row] = bb.x; sB[fc*4+1][row] = bb.y;
            sB[fc*4+2][row] = bb.z; sB[fc*4+3][row] = bb.w;
        }
        __syncthreads();
        #pragma unroll
        for (int kk = 0; kk < 16; ++kk) {
            float ar[8], br[8];
            *reinterpret_cast<float4*>(&ar[0]) = *reinterpret_cast<float4*>(&sA[kk][ty*8]);
            *reinterpret_cast<float4*>(&ar[4]) = *reinterpret_cast<float4*>(&sA[kk][ty*8+4]);
            *reinterpret_cast<float4*>(&br[0]) = *reinterpret_cast<float4*>(&sB[kk][tx*8]);
            *reinterpret_cast<float4*>(&br[4]) = *reinterpret_cast<float4*>(&sB[kk][tx*8+4]);
            #pragma unroll
            for (int i = 0; i < 8; ++i)
                #pragma unroll
                for (int j = 0; j < 8; ++j)
                    acc[i][j] += ar[i] * br[j];
        }
    }
    #pragma unroll
    for (int i = 0; i < 8; ++i)
        #pragma unroll
        for (int j = 0; j < 8; ++j)
            g_go[(size_t)(m0 + ty*8 + i) * H_ + n0 + tx*8 + j] = acc[i][j];
}

// ============ 5) out = RMSNorm(o)*gw * go * sigmoid(go) ============
// grid: BL_, 256 threads, one row each
__global__ void final_kernel(const float* __restrict__ gw, float* __restrict__ out) {
    const int m = blockIdx.x;
    const int tid = threadIdx.x;
    const float* orow = &g_o[(size_t)m * H_];
    const float* grow = &g_go[(size_t)m * H_];

    float ss = 0.f;
    float4 ov[2];
    #pragma unroll
    for (int t = 0; t < 2; ++t) {
        ov[t] = *reinterpret_cast<const float4*>(&orow[tid * 8 + t * 4]);
        ss += ov[t].x*ov[t].x + ov[t].y*ov[t].y + ov[t].z*ov[t].z + ov[t].w*ov[t].w;
    }
    #pragma unroll
    for (int o = 16; o > 0; o >>= 1)
        ss += __shfl_xor_sync(0xffffffffu, ss, o);
    __shared__ float red[8];
    __shared__ float s_rs;
    if ((tid & 31) == 0) red[tid >> 5] = ss;
    __syncthreads();
    if (tid == 0) {
        float t = 0.f;
        #pragma unroll
        for (int i = 0; i < 8; ++i) t += red[i];
        s_rs = rsqrtf(t * (1.f / H_) + EPS_);
    }
    __syncthreads();
    const float rs = s_rs;

    #pragma unroll
    for (int t = 0; t < 2; ++t) {
        int j = tid * 8 + t * 4;
        float4 g4 = *reinterpret_cast<const float4*>(&grow[j]);
        float4 w4 = *reinterpret_cast<const float4*>(&gw[j]);
        float4 r;
        r.x = ov[t].x * rs * w4.x * g4.x * sigmoid_f(g4.x);
        r.y = ov[t].y * rs * w4.y * g4.y * sigmoid_f(g4.y);
        r.z = ov[t].z * rs * w4.z * g4.z * sigmoid_f(g4.z);
        r.w = ov[t].w * rs * w4.w * g4.w * sigmoid_f(g4.w);
        *reinterpret_cast<float4*>(&out[(size_t)m * H_ + j]) = r;
    }
}

// ---------------------------------------------------------------------
extern "C" void kernel_launch(void* const* d_in, const int* in_sizes, int n_in,
                              void* d_out, int out_size) {
    const float* x   = (const float*)d_in[0];
    const float* Wq  = (const float*)d_in[1];
    const float* Wk  = (const float*)d_in[2];
    const float* Wog = (const float*)d_in[3];
    const float* Wig = (const float*)d_in[4];
    const float* gw  = (const float*)d_in[5];
    float* out = (float*)d_out;

    proj_kernel  <<<dim3(4, 64),            256>>>(x, Wq, Wk);
    gla_A_kernel <<<dim3(NT_, B_),          256>>>();
    gla_o_kernel <<<dim3(H_/64, NT_, B_),   256>>>(x);
    gemm_go_kernel<<<dim3(H_/128, BL_/128), 256>>>(x, Wog, Wig);
    final_kernel <<<BL_,                    256>>>(gw, out);
}

// round 3
// speedup vs baseline: 1.3683x; 1.3683x over previous
#include <cuda_runtime.h>
#include <cuda_bf16.h>
#include <math.h>
#include <stdint.h>

#define B_ 2
#define L_ 2048
#define H_ 2048
#define K_ 128
#define BL_ (B_*L_)
#define NT_ (L_/64)
#define SCALE_ 0.08838834764831845f
#define EPS_ 1e-5f

// ---------------- scratch (static device allocations) ----------------
__device__ float g_q[BL_*K_];
__device__ float g_k[BL_*K_];
__device__ float g_D[BL_*K_];
__device__ float g_A[B_*NT_*128*64];
__device__ float g_o[BL_*H_];              // GLA output          32 MB
__device__ float g_go[BL_*H_];             // output gate         32 MB
__device__ __nv_bfloat16 g_Ah[BL_*2*H_];   // [o|x] hi
__device__ __nv_bfloat16 g_Al[BL_*2*H_];   // [o|x] lo
__device__ __nv_bfloat16 g_Bh[H_*2*H_];    // [Wog|Wig] hi
__device__ __nv_bfloat16 g_Bl[H_*2*H_];    // [Wog|Wig] lo

__device__ __forceinline__ float sigmoid_f(float v) { return 1.f/(1.f+expf(-v)); }

__device__ __forceinline__ uint32_t smem_u32(const void* p) {
    uint32_t a;
    asm("{ .reg .u64 t; cvta.to.shared.u64 t, %1; cvt.u32.u64 %0, t; }" : "=r"(a) : "l"(p));
    return a;
}
#define CP_ASYNC16(dst, src) asm volatile("cp.async.cg.shared.global [%0], [%1], 16;" :: "r"(dst), "l"(src))
#define CP_COMMIT() asm volatile("cp.async.commit_group;" ::: "memory")
#define CP_WAIT(n)  asm volatile("cp.async.wait_group %0;" :: "n"(n) : "memory")

// ============ 1) q/k projection GEMM ============
__global__ void proj_kernel(const float* __restrict__ x,
                            const float* __restrict__ Wq,
                            const float* __restrict__ Wk) {
    __shared__ float sX[16][64];
    __shared__ float sW[16][64];
    const int m0 = blockIdx.y * 64;
    const int n0 = blockIdx.x * 64;
    const bool is_q = (n0 < 128);
    const float* W = is_q ? Wq : Wk;
    const int j0 = is_q ? n0 : (n0 - 128);
    const int tid = threadIdx.x;
    const int tx = tid & 15, ty = tid >> 4;
    const int lr = tid >> 2, lc = tid & 3;

    float acc[4][4];
    #pragma unroll
    for (int i = 0; i < 4; ++i)
        #pragma unroll
        for (int j = 0; j < 4; ++j) acc[i][j] = 0.f;

    const float* xrow = x + (size_t)(m0 + lr) * H_ + lc * 4;
    const float* wrow = W + (size_t)(j0 + lr) * H_ + lc * 4;

    for (int k0 = 0; k0 < H_; k0 += 16) {
        float4 xa = *reinterpret_cast<const float4*>(xrow + k0);
        float4 wa = *reinterpret_cast<const float4*>(wrow + k0);
        __syncthreads();
        sX[lc*4+0][lr] = xa.x; sX[lc*4+1][lr] = xa.y;
        sX[lc*4+2][lr] = xa.z; sX[lc*4+3][lr] = xa.w;
        sW[lc*4+0][lr] = wa.x; sW[lc*4+1][lr] = wa.y;
        sW[lc*4+2][lr] = wa.z; sW[lc*4+3][lr] = wa.w;
        __syncthreads();
        #pragma unroll
        for (int kk = 0; kk < 16; ++kk) {
            float4 a4 = *reinterpret_cast<float4*>(&sX[kk][ty*4]);
            float4 b4 = *reinterpret_cast<float4*>(&sW[kk][tx*4]);
            float a[4] = {a4.x, a4.y, a4.z, a4.w};
            float b[4] = {b4.x, b4.y, b4.z, b4.w};
            #pragma unroll
            for (int i = 0; i < 4; ++i)
                #pragma unroll
                for (int j = 0; j < 4; ++j)
                    acc[i][j] += a[i] * b[j];
        }
    }
    #pragma unroll
    for (int i = 0; i < 4; ++i) {
        int row = m0 + ty*4 + i;
        #pragma unroll
        for (int j = 0; j < 4; ++j) {
            int col = j0 + tx*4 + j;
            float v = acc[i][j];
            if (is_q) {
                g_q[row*K_ + col] = v * sigmoid_f(v) * SCALE_;
            } else {
                float ks = sigmoid_f(v);
                g_k[row*K_ + col] = ks;
                g_D[row*K_ + col] = 1.f / (1.f + expf(ks));
            }
        }
    }
}

// ============ 2) banded score matrix A[t,s] ============
__global__ void gla_A_kernel() {
    const int tt = blockIdx.x, b = blockIdx.y;
    const int T0 = tt * 64;
    const int base = b * L_;
    const int tid = threadIdx.x;

    __shared__ float skT[128][80];
    __shared__ float sqT[128][16];

    float* At = &g_A[(size_t)(b * NT_ + tt) * 128 * 64];
    for (int idx = tid; idx < 128 * 64; idx += 256) At[idx] = 0.f;

    for (int sub = 0; sub < 4; ++sub) {
        const int Ti = T0 + sub * 16;
        __syncthreads();
        for (int idx = tid; idx < 79 * 128; idx += 256) {
            int si = idx >> 7;
            int k  = idx & 127;
            int s  = Ti - 63 + si;
            skT[k][si] = (s >= 0) ? g_k[(base + s) * K_ + k] : 0.f;
        }
        __syncthreads();
        if (tid < 128) {
            int k = tid;
            float p = 1.f;
            for (int si = 62; si >= 0; --si) {
                int u = Ti - 62 + si;
                float d = (u >= 0) ? g_D[(base + u) * K_ + k] : 1.f;
                p *= d;
                skT[k][si] *= p;
            }
        } else {
            int k = tid - 128;
            sqT[k][0] = g_q[(base + Ti) * K_ + k];
            float ap = 1.f;
            #pragma unroll
            for (int j = 1; j < 16; ++j) {
                int u = Ti + j;
                ap *= g_D[(base + u) * K_ + k];
                sqT[k][j] = g_q[(base + u) * K_ + k] * ap;
                skT[k][63 + j] *= (1.f / ap);
            }
        }
        __syncthreads();
        for (int r = 0; r < 5; ++r) {
            int p  = r * 256 + tid;
            int ti = p / 80;
            int si = p - ti * 80;
            if (si < 79 && si >= ti && si <= ti + 63) {
                float acc = 0.f;
                #pragma unroll 16
                for (int k = 0; k < 128; ++k)
                    acc += sqT[k][ti] * skT[k][si];
                int sidx = sub * 16 + 1 + si;
                At[sidx * 64 + sub * 16 + ti] = acc;
            }
        }
    }
}

// ============ 3) o = A_band @ X ============
__global__ void gla_o_kernel(const float* __restrict__ x) {
    const int vt = blockIdx.x, tt = blockIdx.y, b = blockIdx.z;
    const int T0 = tt * 64, v0 = vt * 64;
    const float* At = &g_A[(size_t)(b * NT_ + tt) * 128 * 64];

    __shared__ float sA[16][64];
    __shared__ float sV[16][64];
    const int tid = threadIdx.x;
    const int tx = tid & 15, ty = tid >> 4;

    float acc[4][4];
    #pragma unroll
    for (int i = 0; i < 4; ++i)
        #pragma unroll
        for (int j = 0; j < 4; ++j) acc[i][j] = 0.f;

    for (int ks = 0; ks < 8; ++ks) {
        __syncthreads();
        #pragma unroll
        for (int s4 = 0; s4 < 4; ++s4) {
            int id = tid + s4 * 256;
            int kk = id >> 6, c = id & 63;
            sA[kk][c] = At[(ks * 16 + kk) * 64 + c];
        }
        #pragma unroll
        for (int s4 = 0; s4 < 4; ++s4) {
            int id = tid + s4 * 256;
            int kk = id >> 6, c = id & 63;
            int s = T0 - 64 + ks * 16 + kk;
            sV[kk][c] = (s >= 0) ? x[((size_t)(b * L_ + s)) * H_ + v0 + c] : 0.f;
        }
        __syncthreads();
        #pragma unroll
        for (int kk = 0; kk < 16; ++kk) {
            float4 a4 = *reinterpret_cast<float4*>(&sA[kk][ty*4]);
            float4 v4 = *reinterpret_cast<float4*>(&sV[kk][tx*4]);
            float a[4] = {a4.x, a4.y, a4.z, a4.w};
            float v[4] = {v4.x, v4.y, v4.z, v4.w};
            #pragma unroll
            for (int i = 0; i < 4; ++i)
                #pragma unroll
                for (int j = 0; j < 4; ++j)
                    acc[i][j] += a[i] * v[j];
        }
    }
    #pragma unroll
    for (int i = 0; i < 4; ++i)
        #pragma unroll
        for (int j = 0; j < 4; ++j)
            g_o[((size_t)(b * L_ + T0 + ty*4 + i)) * H_ + v0 + tx*4 + j] = acc[i][j];
}

// ============ 4a) split fp32 -> bf16 hi/lo for A = [o | x] ============
__global__ void convA_kernel(const float* __restrict__ x) {
    int idx4 = blockIdx.x * 256 + threadIdx.x;
    int row = idx4 >> 10;
    int col = (idx4 & 1023) * 4;
    const float* src = (col < H_) ? &g_o[(size_t)row * H_ + col]
                                  : &x[(size_t)row * H_ + (col - H_)];
    float4 v = *reinterpret_cast<const float4*>(src);
    float a[4] = {v.x, v.y, v.z, v.w};
    __nv_bfloat16 h[4], l[4];
    #pragma unroll
    for (int i = 0; i < 4; ++i) {
        h[i] = __float2bfloat16(a[i]);
        l[i] = __float2bfloat16(a[i] - __bfloat162float(h[i]));
    }
    size_t o = (size_t)row * (2*H_) + col;
    __nv_bfloat162 p;
    p.x = h[0]; p.y = h[1]; *reinterpret_cast<__nv_bfloat162*>(&g_Ah[o])   = p;
    p.x = h[2]; p.y = h[3]; *reinterpret_cast<__nv_bfloat162*>(&g_Ah[o+2]) = p;
    p.x = l[0]; p.y = l[1]; *reinterpret_cast<__nv_bfloat162*>(&g_Al[o])   = p;
    p.x = l[2]; p.y = l[3]; *reinterpret_cast<__nv_bfloat162*>(&g_Al[o+2]) = p;
}

// ============ 4b) split for B = [Wog | Wig] ============
__global__ void convB_kernel(const float* __restrict__ Wog,
                             const float* __restrict__ Wig) {
    int idx4 = blockIdx.x * 256 + threadIdx.x;
    int row = idx4 >> 10;
    int col = (idx4 & 1023) * 4;
    const float* src = (col < H_) ? &Wog[(size_t)row * H_ + col]
                                  : &Wig[(size_t)row * H_ + (col - H_)];
    float4 v = *reinterpret_cast<const float4*>(src);
    float a[4] = {v.x, v.y, v.z, v.w};
    __nv_bfloat16 h[4], l[4];
    #pragma unroll
    for (int i = 0; i < 4; ++i) {
        h[i] = __float2bfloat16(a[i]);
        l[i] = __float2bfloat16(a[i] - __bfloat162float(h[i]));
    }
    size_t o = (size_t)row * (2*H_) + col;
    __nv_bfloat162 p;
    p.x = h[0]; p.y = h[1]; *reinterpret_cast<__nv_bfloat162*>(&g_Bh[o])   = p;
    p.x = h[2]; p.y = h[3]; *reinterpret_cast<__nv_bfloat162*>(&g_Bh[o+2]) = p;
    p.x = l[0]; p.y = l[1]; *reinterpret_cast<__nv_bfloat162*>(&g_Bl[o])   = p;
    p.x = l[2]; p.y = l[3]; *reinterpret_cast<__nv_bfloat162*>(&g_Bl[o+2]) = p;
}

// ============ 4c) mma.sync bf16 GEMM: go = Ah*Bh + Al*Bh + Ah*Bl ============
// CTA tile 128x128, BK=32, 4 stages, 8 warps (warp tile 64x32)
#define G_ITERS  384            // 3 terms x 128 chunks of 32
#define G_PITCH  80             // bytes per smem row (32 bf16 = 64B, padded)
#define G_ATILE  (128*G_PITCH)  // 10240
#define G_STAGE  (2*G_ATILE)    // 20480
#define G_SMEM   (4*G_STAGE)    // 81920

__device__ __forceinline__ void g_load_stage(uint32_t sbase, int stage, int it,
                                             int m0, int n0, int tid) {
    const int term = it >> 7;
    const int kofs = (it & 127) * 32;
    const __nv_bfloat16* Ap = (term == 1) ? g_Al : g_Ah;
    const __nv_bfloat16* Bp = (term == 2) ? g_Bl : g_Bh;
    const uint32_t sA = sbase + stage * G_STAGE;
    const uint32_t sB = sA + G_ATILE;
    #pragma unroll
    for (int i = 0; i < 2; ++i) {
        int g = tid + i * 256;
        int r = g >> 2, c = g & 3;
        CP_ASYNC16(sA + r * G_PITCH + c * 16,
                   Ap + (size_t)(m0 + r) * (2*H_) + kofs + c * 8);
    }
    #pragma unroll
    for (int i = 0; i < 2; ++i) {
        int g = tid + i * 256;
        int r = g >> 2, c = g & 3;
        CP_ASYNC16(sB + r * G_PITCH + c * 16,
                   Bp + (size_t)(n0 + r) * (2*H_) + kofs + c * 8);
    }
}

__global__ void __launch_bounds__(256, 2) gemm_tc_kernel() {
    extern __shared__ char smem[];
    const uint32_t sbase = smem_u32(smem);
    const int tid = threadIdx.x;
    const int lane = tid & 31;
    const int wid = tid >> 5;
    const int wm = wid & 1;          // 2 warps in m
    const int wn = wid >> 1;         // 4 warps in n
    const int m0 = blockIdx.y * 128;
    const int n0 = blockIdx.x * 128;

    // ldmatrix lane addressing (within tile, before stage offset)
    const uint32_t aAddr = (uint32_t)((wm*64 + (lane & 15)) * G_PITCH + ((lane >> 4) & 1) * 16);
    const uint32_t bAddr = (uint32_t)(G_ATILE +
                    (wn*32 + (lane & 7) + ((lane & 16) ? 8 : 0)) * G_PITCH +
                    ((lane & 8) ? 16 : 0));

    float c[4][4][4];
    #pragma unroll
    for (int i = 0; i < 4; ++i)
        #pragma unroll
        for (int j = 0; j < 4; ++j)
            #pragma unroll
            for (int q = 0; q < 4; ++q) c[i][j][q] = 0.f;

    // prologue: stages 0..2
    #pragma unroll
    for (int s = 0; s < 3; ++s) {
        g_load_stage(sbase, s, s, m0, n0, tid);
        CP_COMMIT();
    }

    #pragma unroll 1
    for (int it = 0; it < G_ITERS; ++it) {
        CP_WAIT(2);
        __syncthreads();
        if (it + 3 < G_ITERS)
            g_load_stage(sbase, (it + 3) & 3, it + 3, m0, n0, tid);
        CP_COMMIT();

        const uint32_t stoff = sbase + (it & 3) * G_STAGE;
        #pragma unroll
        for (int ks = 0; ks < 2; ++ks) {
            uint32_t af[4][4];
            #pragma unroll
            for (int mi = 0; mi < 4; ++mi) {
                asm volatile("ldmatrix.sync.aligned.m8n8.x4.shared.b16 {%0,%1,%2,%3}, [%4];"
                    : "=r"(af[mi][0]), "=r"(af[mi][1]), "=r"(af[mi][2]), "=r"(af[mi][3])
                    : "r"(stoff + aAddr + mi * (16*G_PITCH) + ks * 32));
            }
            uint32_t bf[4][2];
            #pragma unroll
            for (int p = 0; p < 2; ++p) {
                asm volatile("ldmatrix.sync.aligned.m8n8.x4.shared.b16 {%0,%1,%2,%3}, [%4];"
                    : "=r"(bf[p*2][0]), "=r"(bf[p*2][1]), "=r"(bf[p*2+1][0]), "=r"(bf[p*2+1][1])
                    : "r"(stoff + bAddr + p * (16*G_PITCH) + ks * 32));
            }
            #pragma unroll
            for (int mi = 0; mi < 4; ++mi)
                #pragma unroll
                for (int ni = 0; ni < 4; ++ni) {
                    asm volatile(
                        "mma.sync.aligned.m16n8k16.row.col.f32.bf16.bf16.f32 "
                        "{%0,%1,%2,%3}, {%4,%5,%6,%7}, {%8,%9}, {%0,%1,%2,%3};"
                        : "+f"(c[mi][ni][0]), "+f"(c[mi][ni][1]),
                          "+f"(c[mi][ni][2]), "+f"(c[mi][ni][3])
                        : "r"(af[mi][0]), "r"(af[mi][1]), "r"(af[mi][2]), "r"(af[mi][3]),
                          "r"(bf[ni][0]), "r"(bf[ni][1]));
                }
        }
    }

    // epilogue: direct stores
    const int gid = lane >> 2, tig = lane & 3;
    #pragma unroll
    for (int mi = 0; mi < 4; ++mi) {
        #pragma unroll
        for (int ni = 0; ni < 4; ++ni) {
            int row = m0 + wm*64 + mi*16 + gid;
            int col = n0 + wn*32 + ni*8 + tig*2;
            float2 v0 = make_float2(c[mi][ni][0], c[mi][ni][1]);
            float2 v1 = make_float2(c[mi][ni][2], c[mi][ni][3]);
            *reinterpret_cast<float2*>(&g_go[(size_t)row * H_ + col]) = v0;
            *reinterpret_cast<float2*>(&g_go[(size_t)(row + 8) * H_ + col]) = v1;
        }
    }
}

// ============ 5) out = RMSNorm(o)*gw * go * sigmoid(go) ============
__global__ void final_kernel(const float* __restrict__ gw, float* __restrict__ out) {
    const int m = blockIdx.x;
    const int tid = threadIdx.x;
    const float* orow = &g_o[(size_t)m * H_];
    const float* grow = &g_go[(size_t)m * H_];

    float ss = 0.f;
    float4 ov[2];
    #pragma unroll
    for (int t = 0; t < 2; ++t) {
        ov[t] = *reinterpret_cast<const float4*>(&orow[tid * 8 + t * 4]);
        ss += ov[t].x*ov[t].x + ov[t].y*ov[t].y + ov[t].z*ov[t].z + ov[t].w*ov[t].w;
    }
    #pragma unroll
    for (int o = 16; o > 0; o >>= 1)
        ss += __shfl_xor_sync(0xffffffffu, ss, o);
    __shared__ float red[8];
    __shared__ float s_rs;
    if ((tid & 31) == 0) red[tid >> 5] = ss;
    __syncthreads();
    if (tid == 0) {
        float t = 0.f;
        #pragma unroll
        for (int i = 0; i < 8; ++i) t += red[i];
        s_rs = rsqrtf(t * (1.f / H_) + EPS_);
    }
    __syncthreads();
    const float rs = s_rs;

    #pragma unroll
    for (int t = 0; t < 2; ++t) {
        int j = tid * 8 + t * 4;
        float4 g4 = *reinterpret_cast<const float4*>(&grow[j]);
        float4 w4 = *reinterpret_cast<const float4*>(&gw[j]);
        float4 r;
        r.x = ov[t].x * rs * w4.x * g4.x * sigmoid_f(g4.x);
        r.y = ov[t].y * rs * w4.y * g4.y * sigmoid_f(g4.y);
        r.z = ov[t].z * rs * w4.z * g4.z * sigmoid_f(g4.z);
        r.w = ov[t].w * rs * w4.w * g4.w * sigmoid_f(g4.w);
        *reinterpret_cast<float4*>(&out[(size_t)m * H_ + j]) = r;
    }
}

// ---------------------------------------------------------------------
extern "C" void kernel_launch(void* const* d_in, const int* in_sizes, int n_in,
                              void* d_out, int out_size) {
    const float* x   = (const float*)d_in[0];
    const float* Wq  = (const float*)d_in[1];
    const float* Wk  = (const float*)d_in[2];
    const float* Wog = (const float*)d_in[3];
    const float* Wig = (const float*)d_in[4];
    const float* gw  = (const float*)d_in[5];
    float* out = (float*)d_out;

    cudaFuncSetAttribute(gemm_tc_kernel, cudaFuncAttributeMaxDynamicSharedMemorySize, G_SMEM);

    proj_kernel  <<<dim3(4, 64),            256>>>(x, Wq, Wk);
    gla_A_kernel <<<dim3(NT_, B_),          256>>>();
    gla_o_kernel <<<dim3(H_/64, NT_, B_),   256>>>(x);
    convB_kernel <<<(H_*2*H_/4)/256,        256>>>(Wog, Wig);
    convA_kernel <<<(BL_*2*H_/4)/256,       256>>>(x);
    gemm_tc_kernel<<<dim3(H_/128, BL_/128), 256, G_SMEM>>>();
    final_kernel <<<BL_,                    256>>>(gw, out);
}

// round 4
// speedup vs baseline: 2.4121x; 1.7628x over previous
#include <cuda_runtime.h>
#include <cuda_fp16.h>
#include <math.h>
#include <stdint.h>

#define B_ 2
#define L_ 2048
#define H_ 2048
#define K_ 128
#define BL_ (B_*L_)
#define NT_ (L_/64)
#define SCALE_ 0.08838834764831845f
#define EPS_ 1e-5f

// ---------------- scratch (static device allocations) ----------------
__device__ float g_q[BL_*K_];
__device__ float g_k[BL_*K_];
__device__ float g_D[BL_*K_];
__device__ float g_A[B_*NT_*128*64];
__device__ float g_o[BL_*H_];          // GLA output          32 MB
__device__ float g_go[BL_*H_];         // output gate         32 MB
__device__ __half g_A16[BL_*2*H_];     // [o|x] fp16          33.5 MB
__device__ __half g_Bh[H_*2*H_];       // [Wog|Wig] hi        16.8 MB
__device__ __half g_Bl[H_*2*H_];       // [Wog|Wig] lo        16.8 MB

__device__ __forceinline__ float sigmoid_f(float v) { return 1.f/(1.f+expf(-v)); }

__device__ __forceinline__ uint32_t smem_u32(const void* p) {
    uint32_t a;
    asm("{ .reg .u64 t; cvta.to.shared.u64 t, %1; cvt.u32.u64 %0, t; }" : "=r"(a) : "l"(p));
    return a;
}
#define CP_ASYNC16(dst, src) asm volatile("cp.async.cg.shared.global [%0], [%1], 16;" :: "r"(dst), "l"(src))
#define CP_COMMIT() asm volatile("cp.async.commit_group;" ::: "memory")
#define CP_WAIT(n)  asm volatile("cp.async.wait_group %0;" :: "n"(n) : "memory")

// ============ 1) q/k projection GEMM ============
__global__ void proj_kernel(const float* __restrict__ x,
                            const float* __restrict__ Wq,
                            const float* __restrict__ Wk) {
    __shared__ float sX[16][64];
    __shared__ float sW[16][64];
    const int m0 = blockIdx.y * 64;
    const int n0 = blockIdx.x * 64;
    const bool is_q = (n0 < 128);
    const float* W = is_q ? Wq : Wk;
    const int j0 = is_q ? n0 : (n0 - 128);
    const int tid = threadIdx.x;
    const int tx = tid & 15, ty = tid >> 4;
    const int lr = tid >> 2, lc = tid & 3;

    float acc[4][4];
    #pragma unroll
    for (int i = 0; i < 4; ++i)
        #pragma unroll
        for (int j = 0; j < 4; ++j) acc[i][j] = 0.f;

    const float* xrow = x + (size_t)(m0 + lr) * H_ + lc * 4;
    const float* wrow = W + (size_t)(j0 + lr) * H_ + lc * 4;

    for (int k0 = 0; k0 < H_; k0 += 16) {
        float4 xa = *reinterpret_cast<const float4*>(xrow + k0);
        float4 wa = *reinterpret_cast<const float4*>(wrow + k0);
        __syncthreads();
        sX[lc*4+0][lr] = xa.x; sX[lc*4+1][lr] = xa.y;
        sX[lc*4+2][lr] = xa.z; sX[lc*4+3][lr] = xa.w;
        sW[lc*4+0][lr] = wa.x; sW[lc*4+1][lr] = wa.y;
        sW[lc*4+2][lr] = wa.z; sW[lc*4+3][lr] = wa.w;
        __syncthreads();
        #pragma unroll
        for (int kk = 0; kk < 16; ++kk) {
            float4 a4 = *reinterpret_cast<float4*>(&sX[kk][ty*4]);
            float4 b4 = *reinterpret_cast<float4*>(&sW[kk][tx*4]);
            float a[4] = {a4.x, a4.y, a4.z, a4.w};
            float b[4] = {b4.x, b4.y, b4.z, b4.w};
            #pragma unroll
            for (int i = 0; i < 4; ++i)
                #pragma unroll
                for (int j = 0; j < 4; ++j)
                    acc[i][j] += a[i] * b[j];
        }
    }
    #pragma unroll
    for (int i = 0; i < 4; ++i) {
        int row = m0 + ty*4 + i;
        #pragma unroll
        for (int j = 0; j < 4; ++j) {
            int col = j0 + tx*4 + j;
            float v = acc[i][j];
            if (is_q) {
                g_q[row*K_ + col] = v * sigmoid_f(v) * SCALE_;
            } else {
                float ks = sigmoid_f(v);
                g_k[row*K_ + col] = ks;
                g_D[row*K_ + col] = 1.f / (1.f + expf(ks));
            }
        }
    }
}

// ============ 2) banded score matrix A[t,s] ============
__global__ void gla_A_kernel() {
    const int tt = blockIdx.x, b = blockIdx.y;
    const int T0 = tt * 64;
    const int base = b * L_;
    const int tid = threadIdx.x;

    __shared__ float skT[128][80];
    __shared__ float sqT[128][16];

    float* At = &g_A[(size_t)(b * NT_ + tt) * 128 * 64];
    for (int idx = tid; idx < 128 * 64; idx += 256) At[idx] = 0.f;

    for (int sub = 0; sub < 4; ++sub) {
        const int Ti = T0 + sub * 16;
        __syncthreads();
        for (int idx = tid; idx < 79 * 128; idx += 256) {
            int si = idx >> 7;
            int k  = idx & 127;
            int s  = Ti - 63 + si;
            skT[k][si] = (s >= 0) ? g_k[(base + s) * K_ + k] : 0.f;
        }
        __syncthreads();
        if (tid < 128) {
            int k = tid;
            float p = 1.f;
            for (int si = 62; si >= 0; --si) {
                int u = Ti - 62 + si;
                float d = (u >= 0) ? g_D[(base + u) * K_ + k] : 1.f;
                p *= d;
                skT[k][si] *= p;
            }
        } else {
            int k = tid - 128;
            sqT[k][0] = g_q[(base + Ti) * K_ + k];
            float ap = 1.f;
            #pragma unroll
            for (int j = 1; j < 16; ++j) {
                int u = Ti + j;
                ap *= g_D[(base + u) * K_ + k];
                sqT[k][j] = g_q[(base + u) * K_ + k] * ap;
                skT[k][63 + j] *= (1.f / ap);
            }
        }
        __syncthreads();
        for (int r = 0; r < 5; ++r) {
            int p  = r * 256 + tid;
            int ti = p / 80;
            int si = p - ti * 80;
            if (si < 79 && si >= ti && si <= ti + 63) {
                float acc = 0.f;
                #pragma unroll 16
                for (int k = 0; k < 128; ++k)
                    acc += sqT[k][ti] * skT[k][si];
                int sidx = sub * 16 + 1 + si;
                At[sidx * 64 + sub * 16 + ti] = acc;
            }
        }
    }
}

// ============ 3) o = A_band @ X ============
__global__ void gla_o_kernel(const float* __restrict__ x) {
    const int vt = blockIdx.x, tt = blockIdx.y, b = blockIdx.z;
    const int T0 = tt * 64, v0 = vt * 64;
    const float* At = &g_A[(size_t)(b * NT_ + tt) * 128 * 64];

    __shared__ float sA[16][64];
    __shared__ float sV[16][64];
    const int tid = threadIdx.x;
    const int tx = tid & 15, ty = tid >> 4;

    float acc[4][4];
    #pragma unroll
    for (int i = 0; i < 4; ++i)
        #pragma unroll
        for (int j = 0; j < 4; ++j) acc[i][j] = 0.f;

    for (int ks = 0; ks < 8; ++ks) {
        __syncthreads();
        #pragma unroll
        for (int s4 = 0; s4 < 4; ++s4) {
            int id = tid + s4 * 256;
            int kk = id >> 6, c = id & 63;
            sA[kk][c] = At[(ks * 16 + kk) * 64 + c];
        }
        #pragma unroll
        for (int s4 = 0; s4 < 4; ++s4) {
            int id = tid + s4 * 256;
            int kk = id >> 6, c = id & 63;
            int s = T0 - 64 + ks * 16 + kk;
            sV[kk][c] = (s >= 0) ? x[((size_t)(b * L_ + s)) * H_ + v0 + c] : 0.f;
        }
        __syncthreads();
        #pragma unroll
        for (int kk = 0; kk < 16; ++kk) {
            float4 a4 = *reinterpret_cast<float4*>(&sA[kk][ty*4]);
            float4 v4 = *reinterpret_cast<float4*>(&sV[kk][tx*4]);
            float a[4] = {a4.x, a4.y, a4.z, a4.w};
            float v[4] = {v4.x, v4.y, v4.z, v4.w};
            #pragma unroll
            for (int i = 0; i < 4; ++i)
                #pragma unroll
                for (int j = 0; j < 4; ++j)
                    acc[i][j] += a[i] * v[j];
        }
    }
    #pragma unroll
    for (int i = 0; i < 4; ++i)
        #pragma unroll
        for (int j = 0; j < 4; ++j)
            g_o[((size_t)(b * L_ + T0 + ty*4 + i)) * H_ + v0 + tx*4 + j] = acc[i][j];
}

// ============ 4a) fp32 -> fp16 for A = [o | x] ============
__global__ void convA_kernel(const float* __restrict__ x) {
    int idx4 = blockIdx.x * 256 + threadIdx.x;
    int row = idx4 >> 10;
    int col = (idx4 & 1023) * 4;
    const float* src = (col < H_) ? &g_o[(size_t)row * H_ + col]
                                  : &x[(size_t)row * H_ + (col - H_)];
    float4 v = *reinterpret_cast<const float4*>(src);
    __half2 p0, p1;
    p0.x = __float2half_rn(v.x); p0.y = __float2half_rn(v.y);
    p1.x = __float2half_rn(v.z); p1.y = __float2half_rn(v.w);
    size_t o = (size_t)row * (2*H_) + col;
    *reinterpret_cast<__half2*>(&g_A16[o])   = p0;
    *reinterpret_cast<__half2*>(&g_A16[o+2]) = p1;
}

// ============ 4b) split fp32 -> fp16 hi/lo for B = [Wog | Wig] ============
__global__ void convB_kernel(const float* __restrict__ Wog,
                             const float* __restrict__ Wig) {
    int idx4 = blockIdx.x * 256 + threadIdx.x;
    int row = idx4 >> 10;
    int col = (idx4 & 1023) * 4;
    const float* src = (col < H_) ? &Wog[(size_t)row * H_ + col]
                                  : &Wig[(size_t)row * H_ + (col - H_)];
    float4 v = *reinterpret_cast<const float4*>(src);
    float a[4] = {v.x, v.y, v.z, v.w};
    __half h[4], l[4];
    #pragma unroll
    for (int i = 0; i < 4; ++i) {
        h[i] = __float2half_rn(a[i]);
        l[i] = __float2half_rn(a[i] - __half2float(h[i]));
    }
    size_t o = (size_t)row * (2*H_) + col;
    __half2 p;
    p.x = h[0]; p.y = h[1]; *reinterpret_cast<__half2*>(&g_Bh[o])   = p;
    p.x = h[2]; p.y = h[3]; *reinterpret_cast<__half2*>(&g_Bh[o+2]) = p;
    p.x = l[0]; p.y = l[1]; *reinterpret_cast<__half2*>(&g_Bl[o])   = p;
    p.x = l[2]; p.y = l[3]; *reinterpret_cast<__half2*>(&g_Bl[o+2]) = p;
}

// ============ 4c) mma.sync fp16 GEMM: go = A*Bh + A*Bl ============
// CTA tile 128x256, BK=32, 4 stages, 8 warps (2m x 4n), warp tile 64x64
#define G_ITERS  256            // 2 terms x 128 chunks of 32
#define G_PITCH  80             // bytes per smem row (32 fp16 = 64B, pad 16)
#define G_ATILE  (128*G_PITCH)  // 10240
#define G_BTILE  (256*G_PITCH)  // 20480
#define G_STAGE  (G_ATILE + G_BTILE)   // 30720
#define G_SMEM   (4*G_STAGE)           // 122880

__device__ __forceinline__ void g_load_stage(uint32_t sbase, int stage, int it,
                                             int m0, int n0, int tid) {
    const int term = it >> 7;                 // 0: Bh, 1: Bl
    const int kofs = (it & 127) * 32;
    const __half* Bp = term ? g_Bl : g_Bh;
    const uint32_t sA = sbase + stage * G_STAGE;
    const uint32_t sB = sA + G_ATILE;
    #pragma unroll
    for (int i = 0; i < 2; ++i) {
        int g = tid + i * 256;
        int r = g >> 2, c = g & 3;
        CP_ASYNC16(sA + r * G_PITCH + c * 16,
                   g_A16 + (size_t)(m0 + r) * (2*H_) + kofs + c * 8);
    }
    #pragma unroll
    for (int i = 0; i < 4; ++i) {
        int g = tid + i * 256;
        int r = g >> 2, c = g & 3;
        CP_ASYNC16(sB + r * G_PITCH + c * 16,
                   Bp + (size_t)(n0 + r) * (2*H_) + kofs + c * 8);
    }
}

__global__ void __launch_bounds__(256, 1) gemm_tc_kernel() {
    extern __shared__ char smem[];
    const uint32_t sbase = smem_u32(smem);
    const int tid = threadIdx.x;
    const int lane = tid & 31;
    const int wid = tid >> 5;
    const int wm = wid & 1;          // 2 warps in m
    const int wn = wid >> 1;         // 4 warps in n
    const int m0 = blockIdx.y * 128;
    const int n0 = blockIdx.x * 256;

    const uint32_t aAddr = (uint32_t)((wm*64 + (lane & 15)) * G_PITCH + ((lane >> 4) & 1) * 16);
    const uint32_t bAddr = (uint32_t)(G_ATILE +
                    (wn*64 + (lane & 7) + ((lane & 16) ? 8 : 0)) * G_PITCH +
                    ((lane & 8) ? 16 : 0));

    float c[4][8][4];
    #pragma unroll
    for (int i = 0; i < 4; ++i)
        #pragma unroll
        for (int j = 0; j < 8; ++j)
            #pragma unroll
            for (int q = 0; q < 4; ++q) c[i][j][q] = 0.f;

    #pragma unroll
    for (int s = 0; s < 3; ++s) {
        g_load_stage(sbase, s, s, m0, n0, tid);
        CP_COMMIT();
    }

    #pragma unroll 1
    for (int it = 0; it < G_ITERS; ++it) {
        CP_WAIT(2);
        __syncthreads();
        if (it + 3 < G_ITERS)
            g_load_stage(sbase, (it + 3) & 3, it + 3, m0, n0, tid);
        CP_COMMIT();

        const uint32_t stoff = sbase + (it & 3) * G_STAGE;
        #pragma unroll
        for (int ks = 0; ks < 2; ++ks) {
            uint32_t af[4][4];
            #pragma unroll
            for (int mi = 0; mi < 4; ++mi) {
                asm volatile("ldmatrix.sync.aligned.m8n8.x4.shared.b16 {%0,%1,%2,%3}, [%4];"
                    : "=r"(af[mi][0]), "=r"(af[mi][1]), "=r"(af[mi][2]), "=r"(af[mi][3])
                    : "r"(stoff + aAddr + mi * (16*G_PITCH) + ks * 32));
            }
            uint32_t bf[8][2];
            #pragma unroll
            for (int p = 0; p < 4; ++p) {
                asm volatile("ldmatrix.sync.aligned.m8n8.x4.shared.b16 {%0,%1,%2,%3}, [%4];"
                    : "=r"(bf[p*2][0]), "=r"(bf[p*2][1]), "=r"(bf[p*2+1][0]), "=r"(bf[p*2+1][1])
                    : "r"(stoff + bAddr + p * (16*G_PITCH) + ks * 32));
            }
            #pragma unroll
            for (int mi = 0; mi < 4; ++mi)
                #pragma unroll
                for (int ni = 0; ni < 8; ++ni) {
                    asm volatile(
                        "mma.sync.aligned.m16n8k16.row.col.f32.f16.f16.f32 "
                        "{%0,%1,%2,%3}, {%4,%5,%6,%7}, {%8,%9}, {%0,%1,%2,%3};"
                        : "+f"(c[mi][ni][0]), "+f"(c[mi][ni][1]),
                          "+f"(c[mi][ni][2]), "+f"(c[mi][ni][3])
                        : "r"(af[mi][0]), "r"(af[mi][1]), "r"(af[mi][2]), "r"(af[mi][3]),
                          "r"(bf[ni][0]), "r"(bf[ni][1]));
                }
        }
    }

    // epilogue: direct stores
    const int gid = lane >> 2, tig = lane & 3;
    #pragma unroll
    for (int mi = 0; mi < 4; ++mi) {
        #pragma unroll
        for (int ni = 0; ni < 8; ++ni) {
            int row = m0 + wm*64 + mi*16 + gid;
            int col = n0 + wn*64 + ni*8 + tig*2;
            float2 v0 = make_float2(c[mi][ni][0], c[mi][ni][1]);
            float2 v1 = make_float2(c[mi][ni][2], c[mi][ni][3]);
            *reinterpret_cast<float2*>(&g_go[(size_t)row * H_ + col]) = v0;
            *reinterpret_cast<float2*>(&g_go[(size_t)(row + 8) * H_ + col]) = v1;
        }
    }
}

// ============ 5) out = RMSNorm(o)*gw * go * sigmoid(go) ============
__global__ void final_kernel(const float* __restrict__ gw, float* __restrict__ out) {
    const int m = blockIdx.x;
    const int tid = threadIdx.x;
    const float* orow = &g_o[(size_t)m * H_];
    const float* grow = &g_go[(size_t)m * H_];

    float ss = 0.f;
    float4 ov[2];
    #pragma unroll
    for (int t = 0; t < 2; ++t) {
        ov[t] = *reinterpret_cast<const float4*>(&orow[tid * 8 + t * 4]);
        ss += ov[t].x*ov[t].x + ov[t].y*ov[t].y + ov[t].z*ov[t].z + ov[t].w*ov[t].w;
    }
    #pragma unroll
    for (int o = 16; o > 0; o >>= 1)
        ss += __shfl_xor_sync(0xffffffffu, ss, o);
    __shared__ float red[8];
    __shared__ float s_rs;
    if ((tid & 31) == 0) red[tid >> 5] = ss;
    __syncthreads();
    if (tid == 0) {
        float t = 0.f;
        #pragma unroll
        for (int i = 0; i < 8; ++i) t += red[i];
        s_rs = rsqrtf(t * (1.f / H_) + EPS_);
    }
    __syncthreads();
    const float rs = s_rs;

    #pragma unroll
    for (int t = 0; t < 2; ++t) {
        int j = tid * 8 + t * 4;
        float4 g4 = *reinterpret_cast<const float4*>(&grow[j]);
        float4 w4 = *reinterpret_cast<const float4*>(&gw[j]);
        float4 r;
        r.x = ov[t].x * rs * w4.x * g4.x * sigmoid_f(g4.x);
        r.y = ov[t].y * rs * w4.y * g4.y * sigmoid_f(g4.y);
        r.z = ov[t].z * rs * w4.z * g4.z * sigmoid_f(g4.z);
        r.w = ov[t].w * rs * w4.w * g4.w * sigmoid_f(g4.w);
        *reinterpret_cast<float4*>(&out[(size_t)m * H_ + j]) = r;
    }
}

// ---------------------------------------------------------------------
extern "C" void kernel_launch(void* const* d_in, const int* in_sizes, int n_in,
                              void* d_out, int out_size) {
    const float* x   = (const float*)d_in[0];
    const float* Wq  = (const float*)d_in[1];
    const float* Wk  = (const float*)d_in[2];
    const float* Wog = (const float*)d_in[3];
    const float* Wig = (const float*)d_in[4];
    const float* gw  = (const float*)d_in[5];
    float* out = (float*)d_out;

    cudaFuncSetAttribute(gemm_tc_kernel, cudaFuncAttributeMaxDynamicSharedMemorySize, G_SMEM);

    proj_kernel  <<<dim3(4, 64),            256>>>(x, Wq, Wk);
    gla_A_kernel <<<dim3(NT_, B_),          256>>>();
    gla_o_kernel <<<dim3(H_/64, NT_, B_),   256>>>(x);
    convB_kernel <<<(H_*2*H_/4)/256,        256>>>(Wog, Wig);
    convA_kernel <<<(BL_*2*H_/4)/256,       256>>>(x);
    gemm_tc_kernel<<<dim3(H_/256, BL_/128), 256, G_SMEM>>>();
    final_kernel <<<BL_,                    256>>>(gw, out);
}

// round 5
// speedup vs baseline: 3.0254x; 1.2543x over previous
#include <cuda_runtime.h>
#include <cuda_fp16.h>
#include <math.h>
#include <stdint.h>

#define B_ 2
#define L_ 2048
#define H_ 2048
#define K_ 128
#define BL_ (B_*L_)
#define NT_ (L_/64)
#define SCALE_ 0.08838834764831845f
#define EPS_ 1e-5f

// ---------------- scratch ----------------
__device__ float g_q[BL_*K_];
__device__ float g_k[BL_*K_];
__device__ float g_D[BL_*K_];
__device__ float g_A[B_*NT_*128*64];
__device__ float g_o[BL_*H_];          // GLA output fp32
__device__ float g_go[BL_*H_];         // output gate fp32
__device__ __half g_O16[BL_*H_];       // o fp16
__device__ __half g_Xh[BL_*H_];        // x hi fp16
__device__ __half g_Xl[BL_*H_];        // x lo fp16
__device__ __half g_Wh[256*H_];        // [Wq;Wk] hi
__device__ __half g_Wl[256*H_];        // [Wq;Wk] lo
__device__ __half g_Bh[H_*2*H_];       // [Wog|Wig] hi
__device__ __half g_Bl[H_*2*H_];       // [Wog|Wig] lo

__device__ __forceinline__ float sigmoid_f(float v) { return 1.f/(1.f+expf(-v)); }

__device__ __forceinline__ uint32_t smem_u32(const void* p) {
    uint32_t a;
    asm("{ .reg .u64 t; cvta.to.shared.u64 t, %1; cvt.u32.u64 %0, t; }" : "=r"(a) : "l"(p));
    return a;
}
#define CP_ASYNC16(dst, src) asm volatile("cp.async.cg.shared.global [%0], [%1], 16;" :: "r"(dst), "l"(src))
#define CP_COMMIT() asm volatile("cp.async.commit_group;" ::: "memory")
#define CP_WAIT(n)  asm volatile("cp.async.wait_group %0;" :: "n"(n) : "memory")

// ============ 0a) x -> fp16 hi/lo ============
__global__ void convX_kernel(const float* __restrict__ x) {
    int idx4 = blockIdx.x * 256 + threadIdx.x;
    float4 v = *reinterpret_cast<const float4*>(x + (size_t)idx4 * 4);
    float a[4] = {v.x, v.y, v.z, v.w};
    __half h[4], l[4];
    #pragma unroll
    for (int i = 0; i < 4; ++i) {
        h[i] = __float2half_rn(a[i]);
        l[i] = __float2half_rn(a[i] - __half2float(h[i]));
    }
    size_t o = (size_t)idx4 * 4;
    __half2 p;
    p.x = h[0]; p.y = h[1]; *reinterpret_cast<__half2*>(&g_Xh[o])   = p;
    p.x = h[2]; p.y = h[3]; *reinterpret_cast<__half2*>(&g_Xh[o+2]) = p;
    p.x = l[0]; p.y = l[1]; *reinterpret_cast<__half2*>(&g_Xl[o])   = p;
    p.x = l[2]; p.y = l[3]; *reinterpret_cast<__half2*>(&g_Xl[o+2]) = p;
}

// ============ 0b) [Wq;Wk] -> fp16 hi/lo ============
__global__ void convW_kernel(const float* __restrict__ Wq,
                             const float* __restrict__ Wk) {
    int idx4 = blockIdx.x * 256 + threadIdx.x;
    int row = idx4 >> 9;                 // 2048 cols / 4
    int col = (idx4 & 511) * 4;
    const float* src = (row < 128) ? &Wq[(size_t)row * H_ + col]
                                   : &Wk[(size_t)(row - 128) * H_ + col];
    float4 v = *reinterpret_cast<const float4*>(src);
    float a[4] = {v.x, v.y, v.z, v.w};
    __half h[4], l[4];
    #pragma unroll
    for (int i = 0; i < 4; ++i) {
        h[i] = __float2half_rn(a[i]);
        l[i] = __float2half_rn(a[i] - __half2float(h[i]));
    }
    size_t o = (size_t)row * H_ + col;
    __half2 p;
    p.x = h[0]; p.y = h[1]; *reinterpret_cast<__half2*>(&g_Wh[o])   = p;
    p.x = h[2]; p.y = h[3]; *reinterpret_cast<__half2*>(&g_Wh[o+2]) = p;
    p.x = l[0]; p.y = l[1]; *reinterpret_cast<__half2*>(&g_Wl[o])   = p;
    p.x = l[2]; p.y = l[3]; *reinterpret_cast<__half2*>(&g_Wl[o+2]) = p;
}

// ============ 1) proj via mma: [q|k] = x @ [Wq;Wk]^T  (3-term split) ============
// tile 128m x 64n, BK=64, 3 stages, 128 threads (4 warps, warp tile 32x64)
#define P_ITERS  96              // 3 terms x 32 chunks of 64
#define P_PITCH  144
#define P_ATILE  (128*P_PITCH)   // 18432
#define P_STAGE  (192*P_PITCH)   // 27648
#define P_SMEM   (3*P_STAGE)     // 82944

__device__ __forceinline__ void p_load_stage(uint32_t sbase, int stage, int it,
                                             int m0, int n0, int tid) {
    const int term = it >> 5;
    const int kofs = (it & 31) * 64;
    const __half* Ap = (term == 1) ? g_Xl : g_Xh;
    const __half* Bp = (term == 2) ? g_Wl : g_Wh;
    const uint32_t sA = sbase + stage * P_STAGE;
    const uint32_t sB = sA + P_ATILE;
    #pragma unroll
    for (int i = 0; i < 8; ++i) {
        int g = tid + i * 128;
        int r = g >> 3, c = g & 7;
        CP_ASYNC16(sA + r * P_PITCH + c * 16,
                   Ap + (size_t)(m0 + r) * H_ + kofs + c * 8);
    }
    #pragma unroll
    for (int i = 0; i < 4; ++i) {
        int g = tid + i * 128;
        int r = g >> 3, c = g & 7;
        CP_ASYNC16(sB + r * P_PITCH + c * 16,
                   Bp + (size_t)(n0 + r) * H_ + kofs + c * 8);
    }
}

__global__ void __launch_bounds__(128, 2) proj_tc_kernel() {
    extern __shared__ char smem[];
    const uint32_t sbase = smem_u32(smem);
    const int tid = threadIdx.x;
    const int lane = tid & 31;
    const int wm = tid >> 5;        // 4 warps in m
    const int m0 = blockIdx.y * 128;
    const int n0 = blockIdx.x * 64;

    const uint32_t aAddr = (uint32_t)((wm*32 + (lane & 15)) * P_PITCH + ((lane >> 4) & 1) * 16);
    const uint32_t bAddr = (uint32_t)(P_ATILE +
                    ((lane & 7) + ((lane & 16) ? 8 : 0)) * P_PITCH +
                    ((lane & 8) ? 16 : 0));

    float c[2][8][4];
    #pragma unroll
    for (int i = 0; i < 2; ++i)
        #pragma unroll
        for (int j = 0; j < 8; ++j)
            #pragma unroll
            for (int q = 0; q < 4; ++q) c[i][j][q] = 0.f;

    p_load_stage(sbase, 0, 0, m0, n0, tid); CP_COMMIT();
    p_load_stage(sbase, 1, 1, m0, n0, tid); CP_COMMIT();

    int stage = 0;
    #pragma unroll 1
    for (int it = 0; it < P_ITERS; ++it) {
        CP_WAIT(1);
        __syncthreads();
        if (it + 2 < P_ITERS) {
            int ns = stage + 2; if (ns >= 3) ns -= 3;
            p_load_stage(sbase, ns, it + 2, m0, n0, tid);
        }
        CP_COMMIT();

        const uint32_t stoff = sbase + stage * P_STAGE;
        #pragma unroll
        for (int ks = 0; ks < 4; ++ks) {
            uint32_t af[2][4];
            #pragma unroll
            for (int mi = 0; mi < 2; ++mi) {
                asm volatile("ldmatrix.sync.aligned.m8n8.x4.shared.b16 {%0,%1,%2,%3}, [%4];"
                    : "=r"(af[mi][0]), "=r"(af[mi][1]), "=r"(af[mi][2]), "=r"(af[mi][3])
                    : "r"(stoff + aAddr + mi * (16*P_PITCH) + ks * 32));
            }
            uint32_t bf[8][2];
            #pragma unroll
            for (int p = 0; p < 4; ++p) {
                asm volatile("ldmatrix.sync.aligned.m8n8.x4.shared.b16 {%0,%1,%2,%3}, [%4];"
                    : "=r"(bf[p*2][0]), "=r"(bf[p*2][1]), "=r"(bf[p*2+1][0]), "=r"(bf[p*2+1][1])
                    : "r"(stoff + bAddr + p * (16*P_PITCH) + ks * 32));
            }
            #pragma unroll
            for (int mi = 0; mi < 2; ++mi)
                #pragma unroll
                for (int ni = 0; ni < 8; ++ni) {
                    asm volatile(
                        "mma.sync.aligned.m16n8k16.row.col.f32.f16.f16.f32 "
                        "{%0,%1,%2,%3}, {%4,%5,%6,%7}, {%8,%9}, {%0,%1,%2,%3};"
                        : "+f"(c[mi][ni][0]), "+f"(c[mi][ni][1]),
                          "+f"(c[mi][ni][2]), "+f"(c[mi][ni][3])
                        : "r"(af[mi][0]), "r"(af[mi][1]), "r"(af[mi][2]), "r"(af[mi][3]),
                          "r"(bf[ni][0]), "r"(bf[ni][1]));
                }
        }
        if (++stage == 3) stage = 0;
    }

    // epilogue with activations
    const int gid = lane >> 2, tig = lane & 3;
    #pragma unroll
    for (int mi = 0; mi < 2; ++mi) {
        #pragma unroll
        for (int ni = 0; ni < 8; ++ni) {
            #pragma unroll
            for (int q = 0; q < 4; ++q) {
                int row = m0 + wm*32 + mi*16 + gid + (q >> 1) * 8;
                int cg  = n0 + ni*8 + tig*2 + (q & 1);
                float v = c[mi][ni][q];
                if (cg < 128) {
                    g_q[row*K_ + cg] = v * sigmoid_f(v) * SCALE_;
                } else {
                    int col = cg - 128;
                    float ks = sigmoid_f(v);
                    g_k[row*K_ + col] = ks;
                    g_D[row*K_ + col] = 1.f / (1.f + expf(ks));
                }
            }
        }
    }
}

// ============ 2) banded score matrix A[t,s] ============
__global__ void gla_A_kernel() {
    const int tt = blockIdx.x, b = blockIdx.y;
    const int T0 = tt * 64;
    const int base = b * L_;
    const int tid = threadIdx.x;

    __shared__ float skT[128][80];
    __shared__ float sqT[128][16];

    float* At = &g_A[(size_t)(b * NT_ + tt) * 128 * 64];
    for (int idx = tid; idx < 128 * 64; idx += 256) At[idx] = 0.f;

    for (int sub = 0; sub < 4; ++sub) {
        const int Ti = T0 + sub * 16;
        __syncthreads();
        for (int idx = tid; idx < 79 * 128; idx += 256) {
            int si = idx >> 7;
            int k  = idx & 127;
            int s  = Ti - 63 + si;
            skT[k][si] = (s >= 0) ? g_k[(base + s) * K_ + k] : 0.f;
        }
        __syncthreads();
        if (tid < 128) {
            int k = tid;
            float p = 1.f;
            for (int si = 62; si >= 0; --si) {
                int u = Ti - 62 + si;
                float d = (u >= 0) ? g_D[(base + u) * K_ + k] : 1.f;
                p *= d;
                skT[k][si] *= p;
            }
        } else {
            int k = tid - 128;
            sqT[k][0] = g_q[(base + Ti) * K_ + k];
            float ap = 1.f;
            #pragma unroll
            for (int j = 1; j < 16; ++j) {
                int u = Ti + j;
                ap *= g_D[(base + u) * K_ + k];
                sqT[k][j] = g_q[(base + u) * K_ + k] * ap;
                skT[k][63 + j] *= (1.f / ap);
            }
        }
        __syncthreads();
        for (int r = 0; r < 5; ++r) {
            int p  = r * 256 + tid;
            int ti = p / 80;
            int si = p - ti * 80;
            if (si < 79 && si >= ti && si <= ti + 63) {
                float acc = 0.f;
                #pragma unroll 16
                for (int k = 0; k < 128; ++k)
                    acc += sqT[k][ti] * skT[k][si];
                int sidx = sub * 16 + 1 + si;
                At[sidx * 64 + sub * 16 + ti] = acc;
            }
        }
    }
}

// ============ 3) o = A_band @ X (also writes fp16 o) ============
__global__ void gla_o_kernel(const float* __restrict__ x) {
    const int vt = blockIdx.x, tt = blockIdx.y, b = blockIdx.z;
    const int T0 = tt * 64, v0 = vt * 64;
    const float* At = &g_A[(size_t)(b * NT_ + tt) * 128 * 64];

    __shared__ float sA[16][64];
    __shared__ float sV[16][64];
    const int tid = threadIdx.x;
    const int tx = tid & 15, ty = tid >> 4;

    float acc[4][4];
    #pragma unroll
    for (int i = 0; i < 4; ++i)
        #pragma unroll
        for (int j = 0; j < 4; ++j) acc[i][j] = 0.f;

    for (int ks = 0; ks < 8; ++ks) {
        __syncthreads();
        #pragma unroll
        for (int s4 = 0; s4 < 4; ++s4) {
            int id = tid + s4 * 256;
            int kk = id >> 6, c = id & 63;
            sA[kk][c] = At[(ks * 16 + kk) * 64 + c];
        }
        #pragma unroll
        for (int s4 = 0; s4 < 4; ++s4) {
            int id = tid + s4 * 256;
            int kk = id >> 6, c = id & 63;
            int s = T0 - 64 + ks * 16 + kk;
            sV[kk][c] = (s >= 0) ? x[((size_t)(b * L_ + s)) * H_ + v0 + c] : 0.f;
        }
        __syncthreads();
        #pragma unroll
        for (int kk = 0; kk < 16; ++kk) {
            float4 a4 = *reinterpret_cast<float4*>(&sA[kk][ty*4]);
            float4 v4 = *reinterpret_cast<float4*>(&sV[kk][tx*4]);
            float a[4] = {a4.x, a4.y, a4.z, a4.w};
            float v[4] = {v4.x, v4.y, v4.z, v4.w};
            #pragma unroll
            for (int i = 0; i < 4; ++i)
                #pragma unroll
                for (int j = 0; j < 4; ++j)
                    acc[i][j] += a[i] * v[j];
        }
    }
    #pragma unroll
    for (int i = 0; i < 4; ++i)
        #pragma unroll
        for (int j = 0; j < 4; ++j) {
            size_t idx = ((size_t)(b * L_ + T0 + ty*4 + i)) * H_ + v0 + tx*4 + j;
            g_o[idx]   = acc[i][j];
            g_O16[idx] = __float2half_rn(acc[i][j]);
        }
}

// ============ 4a) split fp32 -> fp16 hi/lo for B = [Wog | Wig] ============
__global__ void convB_kernel(const float* __restrict__ Wog,
                             const float* __restrict__ Wig) {
    int idx4 = blockIdx.x * 256 + threadIdx.x;
    int row = idx4 >> 10;
    int col = (idx4 & 1023) * 4;
    const float* src = (col < H_) ? &Wog[(size_t)row * H_ + col]
                                  : &Wig[(size_t)row * H_ + (col - H_)];
    float4 v = *reinterpret_cast<const float4*>(src);
    float a[4] = {v.x, v.y, v.z, v.w};
    __half h[4], l[4];
    #pragma unroll
    for (int i = 0; i < 4; ++i) {
        h[i] = __float2half_rn(a[i]);
        l[i] = __float2half_rn(a[i] - __half2float(h[i]));
    }
    size_t o = (size_t)row * (2*H_) + col;
    __half2 p;
    p.x = h[0]; p.y = h[1]; *reinterpret_cast<__half2*>(&g_Bh[o])   = p;
    p.x = h[2]; p.y = h[3]; *reinterpret_cast<__half2*>(&g_Bh[o+2]) = p;
    p.x = l[0]; p.y = l[1]; *reinterpret_cast<__half2*>(&g_Bl[o])   = p;
    p.x = l[2]; p.y = l[3]; *reinterpret_cast<__half2*>(&g_Bl[o+2]) = p;
}

// ============ 4b) mma GEMM: go = [o|x] @ (Bh + Bl)^T ============
// tile 128m x 256n, BK=64, 3 stages, 8 warps (2m x 4n), warp tile 64x64
#define G_ITERS  128             // 2 terms x 64 chunks of 64
#define G_PITCH  144
#define G_ATILE  (128*G_PITCH)   // 18432
#define G_STAGE  (384*G_PITCH)   // 55296
#define G_SMEM   (3*G_STAGE)     // 165888

__device__ __forceinline__ void g_load_stage(uint32_t sbase, int stage, int it,
                                             int m0, int n0, int tid) {
    const int term = it >> 6;                 // 0: Bh, 1: Bl
    const int kofs = (it & 63) * 64;
    const __half* Bp = term ? g_Bl : g_Bh;
    const __half* Ap = (kofs < H_) ? (g_O16 + kofs) : (g_Xh + (kofs - H_));
    const uint32_t sA = sbase + stage * G_STAGE;
    const uint32_t sB = sA + G_ATILE;
    #pragma unroll
    for (int i = 0; i < 4; ++i) {
        int g = tid + i * 256;
        int r = g >> 3, c = g & 7;
        CP_ASYNC16(sA + r * G_PITCH + c * 16,
                   Ap + (size_t)(m0 + r) * H_ + c * 8);
    }
    #pragma unroll
    for (int i = 0; i < 8; ++i) {
        int g = tid + i * 256;
        int r = g >> 3, c = g & 7;
        CP_ASYNC16(sB + r * G_PITCH + c * 16,
                   Bp + (size_t)(n0 + r) * (2*H_) + kofs + c * 8);
    }
}

__global__ void __launch_bounds__(256, 1) gemm_tc_kernel() {
    extern __shared__ char smem[];
    const uint32_t sbase = smem_u32(smem);
    const int tid = threadIdx.x;
    const int lane = tid & 31;
    const int wid = tid >> 5;
    const int wm = wid & 1;
    const int wn = wid >> 1;
    const int m0 = blockIdx.y * 128;
    const int n0 = blockIdx.x * 256;

    const uint32_t aAddr = (uint32_t)((wm*64 + (lane & 15)) * G_PITCH + ((lane >> 4) & 1) * 16);
    const uint32_t bAddr = (uint32_t)(G_ATILE +
                    (wn*64 + (lane & 7) + ((lane & 16) ? 8 : 0)) * G_PITCH +
                    ((lane & 8) ? 16 : 0));

    float c[4][8][4];
    #pragma unroll
    for (int i = 0; i < 4; ++i)
        #pragma unroll
        for (int j = 0; j < 8; ++j)
            #pragma unroll
            for (int q = 0; q < 4; ++q) c[i][j][q] = 0.f;

    g_load_stage(sbase, 0, 0, m0, n0, tid); CP_COMMIT();
    g_load_stage(sbase, 1, 1, m0, n0, tid); CP_COMMIT();

    int stage = 0;
    #pragma unroll 1
    for (int it = 0; it < G_ITERS; ++it) {
        CP_WAIT(1);
        __syncthreads();
        if (it + 2 < G_ITERS) {
            int ns = stage + 2; if (ns >= 3) ns -= 3;
            g_load_stage(sbase, ns, it + 2, m0, n0, tid);
        }
        CP_COMMIT();

        const uint32_t stoff = sbase + stage * G_STAGE;
        #pragma unroll
        for (int ks = 0; ks < 4; ++ks) {
            uint32_t af[4][4];
            #pragma unroll
            for (int mi = 0; mi < 4; ++mi) {
                asm volatile("ldmatrix.sync.aligned.m8n8.x4.shared.b16 {%0,%1,%2,%3}, [%4];"
                    : "=r"(af[mi][0]), "=r"(af[mi][1]), "=r"(af[mi][2]), "=r"(af[mi][3])
                    : "r"(stoff + aAddr + mi * (16*G_PITCH) + ks * 32));
            }
            uint32_t bf[8][2];
            #pragma unroll
            for (int p = 0; p < 4; ++p) {
                asm volatile("ldmatrix.sync.aligned.m8n8.x4.shared.b16 {%0,%1,%2,%3}, [%4];"
                    : "=r"(bf[p*2][0]), "=r"(bf[p*2][1]), "=r"(bf[p*2+1][0]), "=r"(bf[p*2+1][1])
                    : "r"(stoff + bAddr + p * (16*G_PITCH) + ks * 32));
            }
            #pragma unroll
            for (int mi = 0; mi < 4; ++mi)
                #pragma unroll
                for (int ni = 0; ni < 8; ++ni) {
                    asm volatile(
                        "mma.sync.aligned.m16n8k16.row.col.f32.f16.f16.f32 "
                        "{%0,%1,%2,%3}, {%4,%5,%6,%7}, {%8,%9}, {%0,%1,%2,%3};"
                        : "+f"(c[mi][ni][0]), "+f"(c[mi][ni][1]),
                          "+f"(c[mi][ni][2]), "+f"(c[mi][ni][3])
                        : "r"(af[mi][0]), "r"(af[mi][1]), "r"(af[mi][2]), "r"(af[mi][3]),
                          "r"(bf[ni][0]), "r"(bf[ni][1]));
                }
        }
        if (++stage == 3) stage = 0;
    }

    const int gid = lane >> 2, tig = lane & 3;
    #pragma unroll
    for (int mi = 0; mi < 4; ++mi) {
        #pragma unroll
        for (int ni = 0; ni < 8; ++ni) {
            int row = m0 + wm*64 + mi*16 + gid;
            int col = n0 + wn*64 + ni*8 + tig*2;
            float2 v0 = make_float2(c[mi][ni][0], c[mi][ni][1]);
            float2 v1 = make_float2(c[mi][ni][2], c[mi][ni][3]);
            *reinterpret_cast<float2*>(&g_go[(size_t)row * H_ + col]) = v0;
            *reinterpret_cast<float2*>(&g_go[(size_t)(row + 8) * H_ + col]) = v1;
        }
    }
}

// ============ 5) out = RMSNorm(o)*gw * go * sigmoid(go) ============
__global__ void final_kernel(const float* __restrict__ gw, float* __restrict__ out) {
    const int m = blockIdx.x;
    const int tid = threadIdx.x;
    const float* orow = &g_o[(size_t)m * H_];
    const float* grow = &g_go[(size_t)m * H_];

    float ss = 0.f;
    float4 ov[2];
    #pragma unroll
    for (int t = 0; t < 2; ++t) {
        ov[t] = *reinterpret_cast<const float4*>(&orow[tid * 8 + t * 4]);
        ss += ov[t].x*ov[t].x + ov[t].y*ov[t].y + ov[t].z*ov[t].z + ov[t].w*ov[t].w;
    }
    #pragma unroll
    for (int o = 16; o > 0; o >>= 1)
        ss += __shfl_xor_sync(0xffffffffu, ss, o);
    __shared__ float red[8];
    __shared__ float s_rs;
    if ((tid & 31) == 0) red[tid >> 5] = ss;
    __syncthreads();
    if (tid == 0) {
        float t = 0.f;
        #pragma unroll
        for (int i = 0; i < 8; ++i) t += red[i];
        s_rs = rsqrtf(t * (1.f / H_) + EPS_);
    }
    __syncthreads();
    const float rs = s_rs;

    #pragma unroll
    for (int t = 0; t < 2; ++t) {
        int j = tid * 8 + t * 4;
        float4 g4 = *reinterpret_cast<const float4*>(&grow[j]);
        float4 w4 = *reinterpret_cast<const float4*>(&gw[j]);
        float4 r;
        r.x = ov[t].x * rs * w4.x * g4.x * sigmoid_f(g4.x);
        r.y = ov[t].y * rs * w4.y * g4.y * sigmoid_f(g4.y);
        r.z = ov[t].z * rs * w4.z * g4.z * sigmoid_f(g4.z);
        r.w = ov[t].w * rs * w4.w * g4.w * sigmoid_f(g4.w);
        *reinterpret_cast<float4*>(&out[(size_t)m * H_ + j]) = r;
    }
}

// ---------------------------------------------------------------------
extern "C" void kernel_launch(void* const* d_in, const int* in_sizes, int n_in,
                              void* d_out, int out_size) {
    const float* x   = (const float*)d_in[0];
    const float* Wq  = (const float*)d_in[1];
    const float* Wk  = (const float*)d_in[2];
    const float* Wog = (const float*)d_in[3];
    const float* Wig = (const float*)d_in[4];
    const float* gw  = (const float*)d_in[5];
    float* out = (float*)d_out;

    cudaFuncSetAttribute(proj_tc_kernel, cudaFuncAttributeMaxDynamicSharedMemorySize, P_SMEM);
    cudaFuncSetAttribute(gemm_tc_kernel, cudaFuncAttributeMaxDynamicSharedMemorySize, G_SMEM);

    convX_kernel <<<(BL_*H_/4)/256,  256>>>(x);
    convW_kernel <<<(256*H_/4)/256,  256>>>(Wq, Wk);
    proj_tc_kernel<<<dim3(4, 32),    128, P_SMEM>>>();
    gla_A_kernel <<<dim3(NT_, B_),   256>>>();
    gla_o_kernel <<<dim3(H_/64, NT_, B_), 256>>>(x);
    convB_kernel <<<(H_*2*H_/4)/256, 256>>>(Wog, Wig);
    gemm_tc_kernel<<<dim3(H_/256, BL_/128), 256, G_SMEM>>>();
    final_kernel <<<BL_,             256>>>(gw, out);
}

// round 6
// speedup vs baseline: 4.8908x; 1.6166x over previous
#include <cuda_runtime.h>
#include <cuda_fp16.h>
#include <math.h>
#include <stdint.h>

#define B_ 2
#define L_ 2048
#define H_ 2048
#define K_ 128
#define BL_ (B_*L_)
#define NT_ (L_/64)
#define SCALE_ 0.08838834764831845f
#define EPS_ 1e-5f

// ---------------- scratch ----------------
__device__ float g_q[BL_*K_];
__device__ float g_k[BL_*K_];
__device__ float g_D[BL_*K_];
__device__ float g_A[B_*NT_*128*64];
__device__ float g_o[BL_*H_];          // GLA output fp32
__device__ float g_go[BL_*H_];         // output gate fp32
__device__ __half g_O16[BL_*H_];       // o fp16
__device__ __half g_Xh[BL_*H_];        // x hi fp16
__device__ __half g_Xl[BL_*H_];        // x lo fp16
__device__ __half g_Wh[256*H_];        // [Wq;Wk] hi
__device__ __half g_Wl[256*H_];        // [Wq;Wk] lo
__device__ __half g_Bh[H_*2*H_];       // [Wog|Wig] fp16

__device__ __forceinline__ float sigmoid_f(float v) { return 1.f/(1.f+expf(-v)); }

__device__ __forceinline__ uint32_t smem_u32(const void* p) {
    uint32_t a;
    asm("{ .reg .u64 t; cvta.to.shared.u64 t, %1; cvt.u32.u64 %0, t; }" : "=r"(a) : "l"(p));
    return a;
}
#define CP_ASYNC16(dst, src) asm volatile("cp.async.cg.shared.global [%0], [%1], 16;" :: "r"(dst), "l"(src))
#define CP_COMMIT() asm volatile("cp.async.commit_group;" ::: "memory")
#define CP_WAIT(n)  asm volatile("cp.async.wait_group %0;" :: "n"(n) : "memory")

// ============ 0a) x -> fp16 hi/lo ============
__global__ void convX_kernel(const float* __restrict__ x) {
    int idx4 = blockIdx.x * 256 + threadIdx.x;
    float4 v = *reinterpret_cast<const float4*>(x + (size_t)idx4 * 4);
    float a[4] = {v.x, v.y, v.z, v.w};
    __half h[4], l[4];
    #pragma unroll
    for (int i = 0; i < 4; ++i) {
        h[i] = __float2half_rn(a[i]);
        l[i] = __float2half_rn(a[i] - __half2float(h[i]));
    }
    size_t o = (size_t)idx4 * 4;
    __half2 p;
    p.x = h[0]; p.y = h[1]; *reinterpret_cast<__half2*>(&g_Xh[o])   = p;
    p.x = h[2]; p.y = h[3]; *reinterpret_cast<__half2*>(&g_Xh[o+2]) = p;
    p.x = l[0]; p.y = l[1]; *reinterpret_cast<__half2*>(&g_Xl[o])   = p;
    p.x = l[2]; p.y = l[3]; *reinterpret_cast<__half2*>(&g_Xl[o+2]) = p;
}

// ============ 0b) [Wq;Wk] -> fp16 hi/lo ============
__global__ void convW_kernel(const float* __restrict__ Wq,
                             const float* __restrict__ Wk) {
    int idx4 = blockIdx.x * 256 + threadIdx.x;
    int row = idx4 >> 9;
    int col = (idx4 & 511) * 4;
    const float* src = (row < 128) ? &Wq[(size_t)row * H_ + col]
                                   : &Wk[(size_t)(row - 128) * H_ + col];
    float4 v = *reinterpret_cast<const float4*>(src);
    float a[4] = {v.x, v.y, v.z, v.w};
    __half h[4], l[4];
    #pragma unroll
    for (int i = 0; i < 4; ++i) {
        h[i] = __float2half_rn(a[i]);
        l[i] = __float2half_rn(a[i] - __half2float(h[i]));
    }
    size_t o = (size_t)row * H_ + col;
    __half2 p;
    p.x = h[0]; p.y = h[1]; *reinterpret_cast<__half2*>(&g_Wh[o])   = p;
    p.x = h[2]; p.y = h[3]; *reinterpret_cast<__half2*>(&g_Wh[o+2]) = p;
    p.x = l[0]; p.y = l[1]; *reinterpret_cast<__half2*>(&g_Wl[o])   = p;
    p.x = l[2]; p.y = l[3]; *reinterpret_cast<__half2*>(&g_Wl[o+2]) = p;
}

// ============ 1) proj via mma: [q|k] = x @ [Wq;Wk]^T  (3-term split) ============
#define P_ITERS  96
#define P_PITCH  144
#define P_ATILE  (128*P_PITCH)
#define P_STAGE  (192*P_PITCH)
#define P_SMEM   (3*P_STAGE)

__device__ __forceinline__ void p_load_stage(uint32_t sbase, int stage, int it,
                                             int m0, int n0, int tid) {
    const int term = it >> 5;
    const int kofs = (it & 31) * 64;
    const __half* Ap = (term == 1) ? g_Xl : g_Xh;
    const __half* Bp = (term == 2) ? g_Wl : g_Wh;
    const uint32_t sA = sbase + stage * P_STAGE;
    const uint32_t sB = sA + P_ATILE;
    #pragma unroll
    for (int i = 0; i < 8; ++i) {
        int g = tid + i * 128;
        int r = g >> 3, c = g & 7;
        CP_ASYNC16(sA + r * P_PITCH + c * 16,
                   Ap + (size_t)(m0 + r) * H_ + kofs + c * 8);
    }
    #pragma unroll
    for (int i = 0; i < 4; ++i) {
        int g = tid + i * 128;
        int r = g >> 3, c = g & 7;
        CP_ASYNC16(sB + r * P_PITCH + c * 16,
                   Bp + (size_t)(n0 + r) * H_ + kofs + c * 8);
    }
}

__global__ void __launch_bounds__(128, 2) proj_tc_kernel() {
    extern __shared__ char smem[];
    const uint32_t sbase = smem_u32(smem);
    const int tid = threadIdx.x;
    const int lane = tid & 31;
    const int wm = tid >> 5;
    const int m0 = blockIdx.y * 128;
    const int n0 = blockIdx.x * 64;

    const uint32_t aAddr = (uint32_t)((wm*32 + (lane & 15)) * P_PITCH + ((lane >> 4) & 1) * 16);
    const uint32_t bAddr = (uint32_t)(P_ATILE +
                    ((lane & 7) + ((lane & 16) ? 8 : 0)) * P_PITCH +
                    ((lane & 8) ? 16 : 0));

    float c[2][8][4];
    #pragma unroll
    for (int i = 0; i < 2; ++i)
        #pragma unroll
        for (int j = 0; j < 8; ++j)
            #pragma unroll
            for (int q = 0; q < 4; ++q) c[i][j][q] = 0.f;

    p_load_stage(sbase, 0, 0, m0, n0, tid); CP_COMMIT();
    p_load_stage(sbase, 1, 1, m0, n0, tid); CP_COMMIT();

    int stage = 0;
    #pragma unroll 1
    for (int it = 0; it < P_ITERS; ++it) {
        CP_WAIT(1);
        __syncthreads();
        if (it + 2 < P_ITERS) {
            int ns = stage + 2; if (ns >= 3) ns -= 3;
            p_load_stage(sbase, ns, it + 2, m0, n0, tid);
        }
        CP_COMMIT();

        const uint32_t stoff = sbase + stage * P_STAGE;
        #pragma unroll
        for (int ks = 0; ks < 4; ++ks) {
            uint32_t af[2][4];
            #pragma unroll
            for (int mi = 0; mi < 2; ++mi) {
                asm volatile("ldmatrix.sync.aligned.m8n8.x4.shared.b16 {%0,%1,%2,%3}, [%4];"
                    : "=r"(af[mi][0]), "=r"(af[mi][1]), "=r"(af[mi][2]), "=r"(af[mi][3])
                    : "r"(stoff + aAddr + mi * (16*P_PITCH) + ks * 32));
            }
            uint32_t bf[8][2];
            #pragma unroll
            for (int p = 0; p < 4; ++p) {
                asm volatile("ldmatrix.sync.aligned.m8n8.x4.shared.b16 {%0,%1,%2,%3}, [%4];"
                    : "=r"(bf[p*2][0]), "=r"(bf[p*2][1]), "=r"(bf[p*2+1][0]), "=r"(bf[p*2+1][1])
                    : "r"(stoff + bAddr + p * (16*P_PITCH) + ks * 32));
            }
            #pragma unroll
            for (int mi = 0; mi < 2; ++mi)
                #pragma unroll
                for (int ni = 0; ni < 8; ++ni) {
                    asm volatile(
                        "mma.sync.aligned.m16n8k16.row.col.f32.f16.f16.f32 "
                        "{%0,%1,%2,%3}, {%4,%5,%6,%7}, {%8,%9}, {%0,%1,%2,%3};"
                        : "+f"(c[mi][ni][0]), "+f"(c[mi][ni][1]),
                          "+f"(c[mi][ni][2]), "+f"(c[mi][ni][3])
                        : "r"(af[mi][0]), "r"(af[mi][1]), "r"(af[mi][2]), "r"(af[mi][3]),
                          "r"(bf[ni][0]), "r"(bf[ni][1]));
                }
        }
        if (++stage == 3) stage = 0;
    }

    const int gid = lane >> 2, tig = lane & 3;
    #pragma unroll
    for (int mi = 0; mi < 2; ++mi) {
        #pragma unroll
        for (int ni = 0; ni < 8; ++ni) {
            #pragma unroll
            for (int q = 0; q < 4; ++q) {
                int row = m0 + wm*32 + mi*16 + gid + (q >> 1) * 8;
                int cg  = n0 + ni*8 + tig*2 + (q & 1);
                float v = c[mi][ni][q];
                if (cg < 128) {
                    g_q[row*K_ + cg] = v * sigmoid_f(v) * SCALE_;
                } else {
                    int col = cg - 128;
                    float ks = sigmoid_f(v);
                    g_k[row*K_ + col] = ks;
                    g_D[row*K_ + col] = 1.f / (1.f + expf(ks));
                }
            }
        }
    }
}

// ============ 2) banded score matrix A[t,s] — one CTA per 16-row sub-block ============
// grid: (NT_, B_, 4)
__global__ void gla_A_kernel() {
    const int tt = blockIdx.x, b = blockIdx.y, sub = blockIdx.z;
    const int T0 = tt * 64;
    const int Ti = T0 + sub * 16;
    const int base = b * L_;
    const int tid = threadIdx.x;

    __shared__ float skT[128][80];
    __shared__ float sqT[128][16];

    float* At = &g_A[(size_t)(b * NT_ + tt) * 128 * 64];
    // zero this sub-block's column stripe [sub*16, sub*16+16) over all 128 rows
    for (int idx = tid; idx < 128 * 16; idx += 256) {
        int r = idx >> 4, c = idx & 15;
        At[r * 64 + sub * 16 + c] = 0.f;
    }

    // load raw k for s in [Ti-63, Ti+15]
    for (int idx = tid; idx < 79 * 128; idx += 256) {
        int si = idx >> 7;
        int k  = idx & 127;
        int s  = Ti - 63 + si;
        skT[k][si] = (s >= 0) ? g_k[(base + s) * K_ + k] : 0.f;
    }
    __syncthreads();
    if (tid < 128) {
        int k = tid;
        float p = 1.f;
        for (int si = 62; si >= 0; --si) {
            int u = Ti - 62 + si;
            float d = (u >= 0) ? g_D[(base + u) * K_ + k] : 1.f;
            p *= d;
            skT[k][si] *= p;
        }
    } else {
        int k = tid - 128;
        sqT[k][0] = g_q[(base + Ti) * K_ + k];
        float ap = 1.f;
        #pragma unroll
        for (int j = 1; j < 16; ++j) {
            int u = Ti + j;
            ap *= g_D[(base + u) * K_ + k];
            sqT[k][j] = g_q[(base + u) * K_ + k] * ap;
            skT[k][63 + j] *= (1.f / ap);
        }
    }
    __syncthreads();
    for (int r = 0; r < 5; ++r) {
        int p  = r * 256 + tid;
        int ti = p / 80;
        int si = p - ti * 80;
        if (ti < 16 && si < 79 && si >= ti && si <= ti + 63) {
            float acc = 0.f;
            #pragma unroll 16
            for (int k = 0; k < 128; ++k)
                acc += sqT[k][ti] * skT[k][si];
            int sidx = sub * 16 + 1 + si;
            At[sidx * 64 + sub * 16 + ti] = acc;
        }
    }
}

// ============ 3) o = A_band @ X (also writes fp16 o) ============
__global__ void gla_o_kernel(const float* __restrict__ x) {
    const int vt = blockIdx.x, tt = blockIdx.y, b = blockIdx.z;
    const int T0 = tt * 64, v0 = vt * 64;
    const float* At = &g_A[(size_t)(b * NT_ + tt) * 128 * 64];

    __shared__ float sA[16][64];
    __shared__ float sV[16][64];
    const int tid = threadIdx.x;
    const int tx = tid & 15, ty = tid >> 4;

    float acc[4][4];
    #pragma unroll
    for (int i = 0; i < 4; ++i)
        #pragma unroll
        for (int j = 0; j < 4; ++j) acc[i][j] = 0.f;

    for (int ks = 0; ks < 8; ++ks) {
        __syncthreads();
        #pragma unroll
        for (int s4 = 0; s4 < 4; ++s4) {
            int id = tid + s4 * 256;
            int kk = id >> 6, c = id & 63;
            sA[kk][c] = At[(ks * 16 + kk) * 64 + c];
        }
        #pragma unroll
        for (int s4 = 0; s4 < 4; ++s4) {
            int id = tid + s4 * 256;
            int kk = id >> 6, c = id & 63;
            int s = T0 - 64 + ks * 16 + kk;
            sV[kk][c] = (s >= 0) ? x[((size_t)(b * L_ + s)) * H_ + v0 + c] : 0.f;
        }
        __syncthreads();
        #pragma unroll
        for (int kk = 0; kk < 16; ++kk) {
            float4 a4 = *reinterpret_cast<float4*>(&sA[kk][ty*4]);
            float4 v4 = *reinterpret_cast<float4*>(&sV[kk][tx*4]);
            float a[4] = {a4.x, a4.y, a4.z, a4.w};
            float v[4] = {v4.x, v4.y, v4.z, v4.w};
            #pragma unroll
            for (int i = 0; i < 4; ++i)
                #pragma unroll
                for (int j = 0; j < 4; ++j)
                    acc[i][j] += a[i] * v[j];
        }
    }
    #pragma unroll
    for (int i = 0; i < 4; ++i)
        #pragma unroll
        for (int j = 0; j < 4; ++j) {
            size_t idx = ((size_t)(b * L_ + T0 + ty*4 + i)) * H_ + v0 + tx*4 + j;
            g_o[idx]   = acc[i][j];
            g_O16[idx] = __float2half_rn(acc[i][j]);
        }
}

// ============ 4a) fp32 -> fp16 for B = [Wog | Wig] ============
__global__ void convB_kernel(const float* __restrict__ Wog,
                             const float* __restrict__ Wig) {
    int idx4 = blockIdx.x * 256 + threadIdx.x;
    int row = idx4 >> 10;
    int col = (idx4 & 1023) * 4;
    const float* src = (col < H_) ? &Wog[(size_t)row * H_ + col]
                                  : &Wig[(size_t)row * H_ + (col - H_)];
    float4 v = *reinterpret_cast<const float4*>(src);
    __half2 p0, p1;
    p0.x = __float2half_rn(v.x); p0.y = __float2half_rn(v.y);
    p1.x = __float2half_rn(v.z); p1.y = __float2half_rn(v.w);
    size_t o = (size_t)row * (2*H_) + col;
    *reinterpret_cast<__half2*>(&g_Bh[o])   = p0;
    *reinterpret_cast<__half2*>(&g_Bh[o+2]) = p1;
}

// ============ 4b) mma GEMM: go = [o|x] @ Bh^T  (single fp16 term) ============
#define G_ITERS  64
#define G_PITCH  144
#define G_ATILE  (128*G_PITCH)
#define G_STAGE  (384*G_PITCH)
#define G_SMEM   (3*G_STAGE)

__device__ __forceinline__ void g_load_stage(uint32_t sbase, int stage, int it,
                                             int m0, int n0, int tid) {
    const int kofs = it * 64;
    const __half* Ap = (kofs < H_) ? (g_O16 + kofs) : (g_Xh + (kofs - H_));
    const uint32_t sA = sbase + stage * G_STAGE;
    const uint32_t sB = sA + G_ATILE;
    #pragma unroll
    for (int i = 0; i < 4; ++i) {
        int g = tid + i * 256;
        int r = g >> 3, c = g & 7;
        CP_ASYNC16(sA + r * G_PITCH + c * 16,
                   Ap + (size_t)(m0 + r) * H_ + c * 8);
    }
    #pragma unroll
    for (int i = 0; i < 8; ++i) {
        int g = tid + i * 256;
        int r = g >> 3, c = g & 7;
        CP_ASYNC16(sB + r * G_PITCH + c * 16,
                   g_Bh + (size_t)(n0 + r) * (2*H_) + kofs + c * 8);
    }
}

__global__ void __launch_bounds__(256, 1) gemm_tc_kernel() {
    extern __shared__ char smem[];
    const uint32_t sbase = smem_u32(smem);
    const int tid = threadIdx.x;
    const int lane = tid & 31;
    const int wid = tid >> 5;
    const int wm = wid & 1;
    const int wn = wid >> 1;
    const int m0 = blockIdx.y * 128;
    const int n0 = blockIdx.x * 256;

    const uint32_t aAddr = (uint32_t)((wm*64 + (lane & 15)) * G_PITCH + ((lane >> 4) & 1) * 16);
    const uint32_t bAddr = (uint32_t)(G_ATILE +
                    (wn*64 + (lane & 7) + ((lane & 16) ? 8 : 0)) * G_PITCH +
                    ((lane & 8) ? 16 : 0));

    float c[4][8][4];
    #pragma unroll
    for (int i = 0; i < 4; ++i)
        #pragma unroll
        for (int j = 0; j < 8; ++j)
            #pragma unroll
            for (int q = 0; q < 4; ++q) c[i][j][q] = 0.f;

    g_load_stage(sbase, 0, 0, m0, n0, tid); CP_COMMIT();
    g_load_stage(sbase, 1, 1, m0, n0, tid); CP_COMMIT();

    int stage = 0;
    #pragma unroll 1
    for (int it = 0; it < G_ITERS; ++it) {
        CP_WAIT(1);
        __syncthreads();
        if (it + 2 < G_ITERS) {
            int ns = stage + 2; if (ns >= 3) ns -= 3;
            g_load_stage(sbase, ns, it + 2, m0, n0, tid);
        }
        CP_COMMIT();

        const uint32_t stoff = sbase + stage * G_STAGE;
        #pragma unroll
        for (int ks = 0; ks < 4; ++ks) {
            uint32_t af[4][4];
            #pragma unroll
            for (int mi = 0; mi < 4; ++mi) {
                asm volatile("ldmatrix.sync.aligned.m8n8.x4.shared.b16 {%0,%1,%2,%3}, [%4];"
                    : "=r"(af[mi][0]), "=r"(af[mi][1]), "=r"(af[mi][2]), "=r"(af[mi][3])
                    : "r"(stoff + aAddr + mi * (16*G_PITCH) + ks * 32));
            }
            uint32_t bf[8][2];
            #pragma unroll
            for (int p = 0; p < 4; ++p) {
                asm volatile("ldmatrix.sync.aligned.m8n8.x4.shared.b16 {%0,%1,%2,%3}, [%4];"
                    : "=r"(bf[p*2][0]), "=r"(bf[p*2][1]), "=r"(bf[p*2+1][0]), "=r"(bf[p*2+1][1])
                    : "r"(stoff + bAddr + p * (16*G_PITCH) + ks * 32));
            }
            #pragma unroll
            for (int mi = 0; mi < 4; ++mi)
                #pragma unroll
                for (int ni = 0; ni < 8; ++ni) {
                    asm volatile(
                        "mma.sync.aligned.m16n8k16.row.col.f32.f16.f16.f32 "
                        "{%0,%1,%2,%3}, {%4,%5,%6,%7}, {%8,%9}, {%0,%1,%2,%3};"
                        : "+f"(c[mi][ni][0]), "+f"(c[mi][ni][1]),
                          "+f"(c[mi][ni][2]), "+f"(c[mi][ni][3])
                        : "r"(af[mi][0]), "r"(af[mi][1]), "r"(af[mi][2]), "r"(af[mi][3]),
                          "r"(bf[ni][0]), "r"(bf[ni][1]));
                }
        }
        if (++stage == 3) stage = 0;
    }

    const int gid = lane >> 2, tig = lane & 3;
    #pragma unroll
    for (int mi = 0; mi < 4; ++mi) {
        #pragma unroll
        for (int ni = 0; ni < 8; ++ni) {
            int row = m0 + wm*64 + mi*16 + gid;
            int col = n0 + wn*64 + ni*8 + tig*2;
            float2 v0 = make_float2(c[mi][ni][0], c[mi][ni][1]);
            float2 v1 = make_float2(c[mi][ni][2], c[mi][ni][3]);
            *reinterpret_cast<float2*>(&g_go[(size_t)row * H_ + col]) = v0;
            *reinterpret_cast<float2*>(&g_go[(size_t)(row + 8) * H_ + col]) = v1;
        }
    }
}

// ============ 5) out = RMSNorm(o)*gw * go * sigmoid(go) ============
__global__ void final_kernel(const float* __restrict__ gw, float* __restrict__ out) {
    const int m = blockIdx.x;
    const int tid = threadIdx.x;
    const float* orow = &g_o[(size_t)m * H_];
    const float* grow = &g_go[(size_t)m * H_];

    float ss = 0.f;
    float4 ov[2];
    #pragma unroll
    for (int t = 0; t < 2; ++t) {
        ov[t] = *reinterpret_cast<const float4*>(&orow[tid * 8 + t * 4]);
        ss += ov[t].x*ov[t].x + ov[t].y*ov[t].y + ov[t].z*ov[t].z + ov[t].w*ov[t].w;
    }
    #pragma unroll
    for (int o = 16; o > 0; o >>= 1)
        ss += __shfl_xor_sync(0xffffffffu, ss, o);
    __shared__ float red[8];
    __shared__ float s_rs;
    if ((tid & 31) == 0) red[tid >> 5] = ss;
    __syncthreads();
    if (tid == 0) {
        float t = 0.f;
        #pragma unroll
        for (int i = 0; i < 8; ++i) t += red[i];
        s_rs = rsqrtf(t * (1.f / H_) + EPS_);
    }
    __syncthreads();
    const float rs = s_rs;

    #pragma unroll
    for (int t = 0; t < 2; ++t) {
        int j = tid * 8 + t * 4;
        float4 g4 = *reinterpret_cast<const float4*>(&grow[j]);
        float4 w4 = *reinterpret_cast<const float4*>(&gw[j]);
        float4 r;
        r.x = ov[t].x * rs * w4.x * g4.x * sigmoid_f(g4.x);
        r.y = ov[t].y * rs * w4.y * g4.y * sigmoid_f(g4.y);
        r.z = ov[t].z * rs * w4.z * g4.z * sigmoid_f(g4.z);
        r.w = ov[t].w * rs * w4.w * g4.w * sigmoid_f(g4.w);
        *reinterpret_cast<float4*>(&out[(size_t)m * H_ + j]) = r;
    }
}

// ---------------------------------------------------------------------
extern "C" void kernel_launch(void* const* d_in, const int* in_sizes, int n_in,
                              void* d_out, int out_size) {
    const float* x   = (const float*)d_in[0];
    const float* Wq  = (const float*)d_in[1];
    const float* Wk  = (const float*)d_in[2];
    const float* Wog = (const float*)d_in[3];
    const float* Wig = (const float*)d_in[4];
    const float* gw  = (const float*)d_in[5];
    float* out = (float*)d_out;

    cudaFuncSetAttribute(proj_tc_kernel, cudaFuncAttributeMaxDynamicSharedMemorySize, P_SMEM);
    cudaFuncSetAttribute(gemm_tc_kernel, cudaFuncAttributeMaxDynamicSharedMemorySize, G_SMEM);

    convX_kernel <<<(BL_*H_/4)/256,  256>>>(x);
    convW_kernel <<<(256*H_/4)/256,  256>>>(Wq, Wk);
    proj_tc_kernel<<<dim3(4, 32),    128, P_SMEM>>>();
    gla_A_kernel <<<dim3(NT_, B_, 4), 256>>>();
    gla_o_kernel <<<dim3(H_/64, NT_, B_), 256>>>(x);
    convB_kernel <<<(H_*2*H_/4)/256, 256>>>(Wog, Wig);
    gemm_tc_kernel<<<dim3(H_/256, BL_/128), 256, G_SMEM>>>();
    final_kernel <<<BL_,             256>>>(gw, out);
}

// round 7
// speedup vs baseline: 5.3648x; 1.0969x over previous
#include <cuda_runtime.h>
#include <cuda_fp16.h>
#include <math.h>
#include <stdint.h>

#define B_ 2
#define L_ 2048
#define H_ 2048
#define K_ 128
#define BL_ (B_*L_)
#define NT_ (L_/64)
#define SCALE_ 0.08838834764831845f
#define EPS_ 1e-5f

// ---------------- scratch ----------------
__device__ float g_q[BL_*K_];
__device__ float g_k[BL_*K_];
__device__ float g_D[BL_*K_];
__device__ float g_A[B_*NT_*128*64];
__device__ float g_o[BL_*H_];          // GLA output fp32
__device__ float g_go[BL_*H_];         // output gate fp32
__device__ __half g_O16[BL_*H_];       // o fp16
__device__ __half g_Xh[BL_*H_];        // x hi fp16
__device__ __half g_Xl[BL_*H_];        // x lo fp16
__device__ __half g_Wh[256*H_];        // [Wq;Wk] hi
__device__ __half g_Wl[256*H_];        // [Wq;Wk] lo
__device__ __half g_Bh[H_*2*H_];       // [Wog|Wig] fp16

__device__ __forceinline__ float sigmoid_f(float v) { return 1.f/(1.f+expf(-v)); }

__device__ __forceinline__ uint32_t smem_u32(const void* p) {
    uint32_t a;
    asm("{ .reg .u64 t; cvta.to.shared.u64 t, %1; cvt.u32.u64 %0, t; }" : "=r"(a) : "l"(p));
    return a;
}
#define CP_ASYNC16(dst, src) asm volatile("cp.async.cg.shared.global [%0], [%1], 16;" :: "r"(dst), "l"(src))
#define CP_COMMIT() asm volatile("cp.async.commit_group;" ::: "memory")
#define CP_WAIT(n)  asm volatile("cp.async.wait_group %0;" :: "n"(n) : "memory")

// ============ 0a) x -> fp16 hi/lo ============
__global__ void convX_kernel(const float* __restrict__ x) {
    int idx4 = blockIdx.x * 256 + threadIdx.x;
    float4 v = *reinterpret_cast<const float4*>(x + (size_t)idx4 * 4);
    float a[4] = {v.x, v.y, v.z, v.w};
    __half h[4], l[4];
    #pragma unroll
    for (int i = 0; i < 4; ++i) {
        h[i] = __float2half_rn(a[i]);
        l[i] = __float2half_rn(a[i] - __half2float(h[i]));
    }
    size_t o = (size_t)idx4 * 4;
    __half2 p;
    p.x = h[0]; p.y = h[1]; *reinterpret_cast<__half2*>(&g_Xh[o])   = p;
    p.x = h[2]; p.y = h[3]; *reinterpret_cast<__half2*>(&g_Xh[o+2]) = p;
    p.x = l[0]; p.y = l[1]; *reinterpret_cast<__half2*>(&g_Xl[o])   = p;
    p.x = l[2]; p.y = l[3]; *reinterpret_cast<__half2*>(&g_Xl[o+2]) = p;
}

// ============ 0b) [Wq;Wk] -> fp16 hi/lo ============
__global__ void convW_kernel(const float* __restrict__ Wq,
                             const float* __restrict__ Wk) {
    int idx4 = blockIdx.x * 256 + threadIdx.x;
    int row = idx4 >> 9;
    int col = (idx4 & 511) * 4;
    const float* src = (row < 128) ? &Wq[(size_t)row * H_ + col]
                                   : &Wk[(size_t)(row - 128) * H_ + col];
    float4 v = *reinterpret_cast<const float4*>(src);
    float a[4] = {v.x, v.y, v.z, v.w};
    __half h[4], l[4];
    #pragma unroll
    for (int i = 0; i < 4; ++i) {
        h[i] = __float2half_rn(a[i]);
        l[i] = __float2half_rn(a[i] - __half2float(h[i]));
    }
    size_t o = (size_t)row * H_ + col;
    __half2 p;
    p.x = h[0]; p.y = h[1]; *reinterpret_cast<__half2*>(&g_Wh[o])   = p;
    p.x = h[2]; p.y = h[3]; *reinterpret_cast<__half2*>(&g_Wh[o+2]) = p;
    p.x = l[0]; p.y = l[1]; *reinterpret_cast<__half2*>(&g_Wl[o])   = p;
    p.x = l[2]; p.y = l[3]; *reinterpret_cast<__half2*>(&g_Wl[o+2]) = p;
}

// ============ 1) proj via mma: [q|k] = x @ [Wq;Wk]^T  (3-term split) ============
#define P_ITERS  96
#define P_PITCH  144
#define P_ATILE  (128*P_PITCH)
#define P_STAGE  (192*P_PITCH)
#define P_SMEM   (3*P_STAGE)

__device__ __forceinline__ void p_load_stage(uint32_t sbase, int stage, int it,
                                             int m0, int n0, int tid) {
    const int term = it >> 5;
    const int kofs = (it & 31) * 64;
    const __half* Ap = (term == 1) ? g_Xl : g_Xh;
    const __half* Bp = (term == 2) ? g_Wl : g_Wh;
    const uint32_t sA = sbase + stage * P_STAGE;
    const uint32_t sB = sA + P_ATILE;
    #pragma unroll
    for (int i = 0; i < 8; ++i) {
        int g = tid + i * 128;
        int r = g >> 3, c = g & 7;
        CP_ASYNC16(sA + r * P_PITCH + c * 16,
                   Ap + (size_t)(m0 + r) * H_ + kofs + c * 8);
    }
    #pragma unroll
    for (int i = 0; i < 4; ++i) {
        int g = tid + i * 128;
        int r = g >> 3, c = g & 7;
        CP_ASYNC16(sB + r * P_PITCH + c * 16,
                   Bp + (size_t)(n0 + r) * H_ + kofs + c * 8);
    }
}

__global__ void __launch_bounds__(128, 2) proj_tc_kernel() {
    extern __shared__ char smem[];
    const uint32_t sbase = smem_u32(smem);
    const int tid = threadIdx.x;
    const int lane = tid & 31;
    const int wm = tid >> 5;
    const int m0 = blockIdx.y * 128;
    const int n0 = blockIdx.x * 64;

    const uint32_t aAddr = (uint32_t)((wm*32 + (lane & 15)) * P_PITCH + ((lane >> 4) & 1) * 16);
    const uint32_t bAddr = (uint32_t)(P_ATILE +
                    ((lane & 7) + ((lane & 16) ? 8 : 0)) * P_PITCH +
                    ((lane & 8) ? 16 : 0));

    float c[2][8][4];
    #pragma unroll
    for (int i = 0; i < 2; ++i)
        #pragma unroll
        for (int j = 0; j < 8; ++j)
            #pragma unroll
            for (int q = 0; q < 4; ++q) c[i][j][q] = 0.f;

    p_load_stage(sbase, 0, 0, m0, n0, tid); CP_COMMIT();
    p_load_stage(sbase, 1, 1, m0, n0, tid); CP_COMMIT();

    int stage = 0;
    #pragma unroll 1
    for (int it = 0; it < P_ITERS; ++it) {
        CP_WAIT(1);
        __syncthreads();
        if (it + 2 < P_ITERS) {
            int ns = stage + 2; if (ns >= 3) ns -= 3;
            p_load_stage(sbase, ns, it + 2, m0, n0, tid);
        }
        CP_COMMIT();

        const uint32_t stoff = sbase + stage * P_STAGE;
        #pragma unroll
        for (int ks = 0; ks < 4; ++ks) {
            uint32_t af[2][4];
            #pragma unroll
            for (int mi = 0; mi < 2; ++mi) {
                asm volatile("ldmatrix.sync.aligned.m8n8.x4.shared.b16 {%0,%1,%2,%3}, [%4];"
                    : "=r"(af[mi][0]), "=r"(af[mi][1]), "=r"(af[mi][2]), "=r"(af[mi][3])
                    : "r"(stoff + aAddr + mi * (16*P_PITCH) + ks * 32));
            }
            uint32_t bf[8][2];
            #pragma unroll
            for (int p = 0; p < 4; ++p) {
                asm volatile("ldmatrix.sync.aligned.m8n8.x4.shared.b16 {%0,%1,%2,%3}, [%4];"
                    : "=r"(bf[p*2][0]), "=r"(bf[p*2][1]), "=r"(bf[p*2+1][0]), "=r"(bf[p*2+1][1])
                    : "r"(stoff + bAddr + p * (16*P_PITCH) + ks * 32));
            }
            #pragma unroll
            for (int mi = 0; mi < 2; ++mi)
                #pragma unroll
                for (int ni = 0; ni < 8; ++ni) {
                    asm volatile(
                        "mma.sync.aligned.m16n8k16.row.col.f32.f16.f16.f32 "
                        "{%0,%1,%2,%3}, {%4,%5,%6,%7}, {%8,%9}, {%0,%1,%2,%3};"
                        : "+f"(c[mi][ni][0]), "+f"(c[mi][ni][1]),
                          "+f"(c[mi][ni][2]), "+f"(c[mi][ni][3])
                        : "r"(af[mi][0]), "r"(af[mi][1]), "r"(af[mi][2]), "r"(af[mi][3]),
                          "r"(bf[ni][0]), "r"(bf[ni][1]));
                }
        }
        if (++stage == 3) stage = 0;
    }

    const int gid = lane >> 2, tig = lane & 3;
    #pragma unroll
    for (int mi = 0; mi < 2; ++mi) {
        #pragma unroll
        for (int ni = 0; ni < 8; ++ni) {
            #pragma unroll
            for (int q = 0; q < 4; ++q) {
                int row = m0 + wm*32 + mi*16 + gid + (q >> 1) * 8;
                int cg  = n0 + ni*8 + tig*2 + (q & 1);
                float v = c[mi][ni][q];
                if (cg < 128) {
                    g_q[row*K_ + cg] = v * sigmoid_f(v) * SCALE_;
                } else {
                    int col = cg - 128;
                    float ks = sigmoid_f(v);
                    g_k[row*K_ + col] = ks;
                    g_D[row*K_ + col] = 1.f / (1.f + expf(ks));
                }
            }
        }
    }
}

// ============ 2) banded score matrix A[t,s] — one CTA per 16-row sub-block ============
__global__ void gla_A_kernel() {
    const int tt = blockIdx.x, b = blockIdx.y, sub = blockIdx.z;
    const int T0 = tt * 64;
    const int Ti = T0 + sub * 16;
    const int base = b * L_;
    const int tid = threadIdx.x;

    __shared__ float skT[128][80];
    __shared__ float sqT[128][16];

    float* At = &g_A[(size_t)(b * NT_ + tt) * 128 * 64];
    for (int idx = tid; idx < 128 * 16; idx += 256) {
        int r = idx >> 4, c = idx & 15;
        At[r * 64 + sub * 16 + c] = 0.f;
    }

    for (int idx = tid; idx < 79 * 128; idx += 256) {
        int si = idx >> 7;
        int k  = idx & 127;
        int s  = Ti - 63 + si;
        skT[k][si] = (s >= 0) ? g_k[(base + s) * K_ + k] : 0.f;
    }
    __syncthreads();
    if (tid < 128) {
        int k = tid;
        float p = 1.f;
        for (int si = 62; si >= 0; --si) {
            int u = Ti - 62 + si;
            float d = (u >= 0) ? g_D[(base + u) * K_ + k] : 1.f;
            p *= d;
            skT[k][si] *= p;
        }
    } else {
        int k = tid - 128;
        sqT[k][0] = g_q[(base + Ti) * K_ + k];
        float ap = 1.f;
        #pragma unroll
        for (int j = 1; j < 16; ++j) {
            int u = Ti + j;
            ap *= g_D[(base + u) * K_ + k];
            sqT[k][j] = g_q[(base + u) * K_ + k] * ap;
            skT[k][63 + j] *= (1.f / ap);
        }
    }
    __syncthreads();
    for (int r = 0; r < 5; ++r) {
        int p  = r * 256 + tid;
        int ti = p / 80;
        int si = p - ti * 80;
        if (ti < 16 && si < 79 && si >= ti && si <= ti + 63) {
            float acc = 0.f;
            #pragma unroll 16
            for (int k = 0; k < 128; ++k)
                acc += sqT[k][ti] * skT[k][si];
            int sidx = sub * 16 + 1 + si;
            At[sidx * 64 + sub * 16 + ti] = acc;
        }
    }
}

// ============ 3) o = A_band @ X via mma (exact 3-term fp16 split) ============
// grid (H_/256, NT_, B_), 256 thr. CTA: 64 t-rows x 256 v-cols (2 chunks of 128).
#define OV_PITCH 272
#define O_AMAT   (64*OV_PITCH)        // 17408 per A matrix (hi or lo)
#define O_XMAT   (128*OV_PITCH)       // 34816 per X matrix
#define O_STAGE  (2*O_XMAT)           // 69632 (hi+lo)
#define O_XBASE  (2*O_AMAT)
#define O_SMEM   (O_XBASE + 2*O_STAGE)  // 174080

__global__ void __launch_bounds__(256, 1) gla_o_tc_kernel() {
    extern __shared__ char smem[];
    const uint32_t sb = smem_u32(smem);
    const int vt = blockIdx.x, tt = blockIdx.y, b = blockIdx.z;
    const int T0 = tt * 64;
    const int tid = threadIdx.x;
    const int lane = tid & 31, wid = tid >> 5;
    const int wm = wid & 1, wn = wid >> 1;

    // ---- convert A tile [128 sidx][64 t] fp32 -> smem [t][sidx] fp16 hi/lo ----
    const float* At = &g_A[(size_t)(b * NT_ + tt) * 128 * 64];
    #pragma unroll
    for (int i = 0; i < 32; ++i) {
        int idx = tid + i * 256;       // idx = sidx*64 + t
        float v = At[idx];
        int t = idx & 63, sidx = idx >> 6;
        __half h = __float2half_rn(v);
        __half l = __float2half_rn(v - __half2float(h));
        *reinterpret_cast<__half*>(smem + t * OV_PITCH + sidx * 2) = h;
        *reinterpret_cast<__half*>(smem + O_AMAT + t * OV_PITCH + sidx * 2) = l;
    }

    // ---- issue X loads for both chunks ----
    #pragma unroll
    for (int vc = 0; vc < 2; ++vc) {
        const int v0 = vt * 256 + vc * 128;
        const uint32_t sX = sb + O_XBASE + vc * O_STAGE;
        #pragma unroll
        for (int i = 0; i < 8; ++i) {
            int g = tid + i * 256;
            int r = g >> 4, cc = g & 15;
            int srow = T0 - 64 + r;
            size_t grow = (size_t)(b * L_ + (srow < 0 ? 0 : srow)) * H_ + v0 + cc * 8;
            CP_ASYNC16(sX + r * OV_PITCH + cc * 16, g_Xh + grow);
            CP_ASYNC16(sX + O_XMAT + r * OV_PITCH + cc * 16, g_Xl + grow);
        }
        CP_COMMIT();
    }

    const uint32_t aAddr = sb + (uint32_t)((wm*32 + (lane & 15)) * OV_PITCH + ((lane >> 4) & 1) * 16);
    const int gid = lane >> 2, tig = lane & 3;

    #pragma unroll
    for (int vc = 0; vc < 2; ++vc) {
        if (vc == 0) { CP_WAIT(1); } else { CP_WAIT(0); }
        __syncthreads();

        const uint32_t sX = sb + O_XBASE + vc * O_STAGE;
        const uint32_t bAddr = sX + (uint32_t)((lane & 15) * OV_PITCH + (wn*32) * 2);

        float acc[2][4][4];
        #pragma unroll
        for (int i = 0; i < 2; ++i)
            #pragma unroll
            for (int j = 0; j < 4; ++j)
                #pragma unroll
                for (int q = 0; q < 4; ++q) acc[i][j][q] = 0.f;

        #pragma unroll
        for (int ks = 0; ks < 8; ++ks) {
            uint32_t ah[2][4], al[2][4];
            #pragma unroll
            for (int mi = 0; mi < 2; ++mi) {
                asm volatile("ldmatrix.sync.aligned.m8n8.x4.shared.b16 {%0,%1,%2,%3}, [%4];"
                    : "=r"(ah[mi][0]), "=r"(ah[mi][1]), "=r"(ah[mi][2]), "=r"(ah[mi][3])
                    : "r"(aAddr + mi * (16*OV_PITCH) + ks * 32));
                asm volatile("ldmatrix.sync.aligned.m8n8.x4.shared.b16 {%0,%1,%2,%3}, [%4];"
                    : "=r"(al[mi][0]), "=r"(al[mi][1]), "=r"(al[mi][2]), "=r"(al[mi][3])
                    : "r"(aAddr + O_AMAT + mi * (16*OV_PITCH) + ks * 32));
            }
            uint32_t bh[4][2], bl[4][2];
            #pragma unroll
            for (int nf = 0; nf < 4; ++nf) {
                asm volatile("ldmatrix.sync.aligned.m8n8.x2.trans.shared.b16 {%0,%1}, [%2];"
                    : "=r"(bh[nf][0]), "=r"(bh[nf][1])
                    : "r"(bAddr + ks * (16*OV_PITCH) + nf * 16));
                asm volatile("ldmatrix.sync.aligned.m8n8.x2.trans.shared.b16 {%0,%1}, [%2];"
                    : "=r"(bl[nf][0]), "=r"(bl[nf][1])
                    : "r"(bAddr + O_XMAT + ks * (16*OV_PITCH) + nf * 16));
            }
            #pragma unroll
            for (int mi = 0; mi < 2; ++mi)
                #pragma unroll
                for (int nf = 0; nf < 4; ++nf) {
                    asm volatile(
                        "mma.sync.aligned.m16n8k16.row.col.f32.f16.f16.f32 "
                        "{%0,%1,%2,%3}, {%4,%5,%6,%7}, {%8,%9}, {%0,%1,%2,%3};"
                        : "+f"(acc[mi][nf][0]), "+f"(acc[mi][nf][1]),
                          "+f"(acc[mi][nf][2]), "+f"(acc[mi][nf][3])
                        : "r"(ah[mi][0]), "r"(ah[mi][1]), "r"(ah[mi][2]), "r"(ah[mi][3]),
                          "r"(bh[nf][0]), "r"(bh[nf][1]));
                    asm volatile(
                        "mma.sync.aligned.m16n8k16.row.col.f32.f16.f16.f32 "
                        "{%0,%1,%2,%3}, {%4,%5,%6,%7}, {%8,%9}, {%0,%1,%2,%3};"
                        : "+f"(acc[mi][nf][0]), "+f"(acc[mi][nf][1]),
                          "+f"(acc[mi][nf][2]), "+f"(acc[mi][nf][3])
                        : "r"(al[mi][0]), "r"(al[mi][1]), "r"(al[mi][2]), "r"(al[mi][3]),
                          "r"(bh[nf][0]), "r"(bh[nf][1]));
                    asm volatile(
                        "mma.sync.aligned.m16n8k16.row.col.f32.f16.f16.f32 "
                        "{%0,%1,%2,%3}, {%4,%5,%6,%7}, {%8,%9}, {%0,%1,%2,%3};"
                        : "+f"(acc[mi][nf][0]), "+f"(acc[mi][nf][1]),
                          "+f"(acc[mi][nf][2]), "+f"(acc[mi][nf][3])
                        : "r"(ah[mi][0]), "r"(ah[mi][1]), "r"(ah[mi][2]), "r"(ah[mi][3]),
                          "r"(bl[nf][0]), "r"(bl[nf][1]));
                }
        }

        // epilogue for this chunk
        #pragma unroll
        for (int mi = 0; mi < 2; ++mi) {
            #pragma unroll
            for (int nf = 0; nf < 4; ++nf) {
                int row = T0 + wm*32 + mi*16 + gid;
                int col = vt*256 + vc*128 + wn*32 + nf*8 + tig*2;
                size_t i0 = (size_t)(b * L_ + row) * H_ + col;
                size_t i1 = i0 + 8 * H_;
                *reinterpret_cast<float2*>(&g_o[i0]) = make_float2(acc[mi][nf][0], acc[mi][nf][1]);
                *reinterpret_cast<float2*>(&g_o[i1]) = make_float2(acc[mi][nf][2], acc[mi][nf][3]);
                __half2 h0; h0.x = __float2half_rn(acc[mi][nf][0]); h0.y = __float2half_rn(acc[mi][nf][1]);
                __half2 h1; h1.x = __float2half_rn(acc[mi][nf][2]); h1.y = __float2half_rn(acc[mi][nf][3]);
                *reinterpret_cast<__half2*>(&g_O16[i0]) = h0;
                *reinterpret_cast<__half2*>(&g_O16[i1]) = h1;
            }
        }
    }
}

// ============ 4a) fp32 -> fp16 for B = [Wog | Wig] ============
__global__ void convB_kernel(const float* __restrict__ Wog,
                             const float* __restrict__ Wig) {
    int idx4 = blockIdx.x * 256 + threadIdx.x;
    int row = idx4 >> 10;
    int col = (idx4 & 1023) * 4;
    const float* src = (col < H_) ? &Wog[(size_t)row * H_ + col]
                                  : &Wig[(size_t)row * H_ + (col - H_)];
    float4 v = *reinterpret_cast<const float4*>(src);
    __half2 p0, p1;
    p0.x = __float2half_rn(v.x); p0.y = __float2half_rn(v.y);
    p1.x = __float2half_rn(v.z); p1.y = __float2half_rn(v.w);
    size_t o = (size_t)row * (2*H_) + col;
    *reinterpret_cast<__half2*>(&g_Bh[o])   = p0;
    *reinterpret_cast<__half2*>(&g_Bh[o+2]) = p1;
}

// ============ 4b) mma GEMM: go = [o|x] @ Bh^T ============
#define G_ITERS  64
#define G_PITCH  144
#define G_ATILE  (128*G_PITCH)
#define G_STAGE  (384*G_PITCH)
#define G_SMEM   (3*G_STAGE)

__device__ __forceinline__ void g_load_stage(uint32_t sbase, int stage, int it,
                                             int m0, int n0, int tid) {
    const int kofs = it * 64;
    const __half* Ap = (kofs < H_) ? (g_O16 + kofs) : (g_Xh + (kofs - H_));
    const uint32_t sA = sbase + stage * G_STAGE;
    const uint32_t sB = sA + G_ATILE;
    #pragma unroll
    for (int i = 0; i < 4; ++i) {
        int g = tid + i * 256;
        int r = g >> 3, c = g & 7;
        CP_ASYNC16(sA + r * G_PITCH + c * 16,
                   Ap + (size_t)(m0 + r) * H_ + c * 8);
    }
    #pragma unroll
    for (int i = 0; i < 8; ++i) {
        int g = tid + i * 256;
        int r = g >> 3, c = g & 7;
        CP_ASYNC16(sB + r * G_PITCH + c * 16,
                   g_Bh + (size_t)(n0 + r) * (2*H_) + kofs + c * 8);
    }
}

__global__ void __launch_bounds__(256, 1) gemm_tc_kernel() {
    extern __shared__ char smem[];
    const uint32_t sbase = smem_u32(smem);
    const int tid = threadIdx.x;
    const int lane = tid & 31;
    const int wid = tid >> 5;
    const int wm = wid & 1;
    const int wn = wid >> 1;
    const int m0 = blockIdx.y * 128;
    const int n0 = blockIdx.x * 256;

    const uint32_t aAddr = (uint32_t)((wm*64 + (lane & 15)) * G_PITCH + ((lane >> 4) & 1) * 16);
    const uint32_t bAddr = (uint32_t)(G_ATILE +
                    (wn*64 + (lane & 7) + ((lane & 16) ? 8 : 0)) * G_PITCH +
                    ((lane & 8) ? 16 : 0));

    float c[4][8][4];
    #pragma unroll
    for (int i = 0; i < 4; ++i)
        #pragma unroll
        for (int j = 0; j < 8; ++j)
            #pragma unroll
            for (int q = 0; q < 4; ++q) c[i][j][q] = 0.f;

    g_load_stage(sbase, 0, 0, m0, n0, tid); CP_COMMIT();
    g_load_stage(sbase, 1, 1, m0, n0, tid); CP_COMMIT();

    int stage = 0;
    #pragma unroll 1
    for (int it = 0; it < G_ITERS; ++it) {
        CP_WAIT(1);
        __syncthreads();
        if (it + 2 < G_ITERS) {
            int ns = stage + 2; if (ns >= 3) ns -= 3;
            g_load_stage(sbase, ns, it + 2, m0, n0, tid);
        }
        CP_COMMIT();

        const uint32_t stoff = sbase + stage * G_STAGE;
        #pragma unroll
        for (int ks = 0; ks < 4; ++ks) {
            uint32_t af[4][4];
            #pragma unroll
            for (int mi = 0; mi < 4; ++mi) {
                asm volatile("ldmatrix.sync.aligned.m8n8.x4.shared.b16 {%0,%1,%2,%3}, [%4];"
                    : "=r"(af[mi][0]), "=r"(af[mi][1]), "=r"(af[mi][2]), "=r"(af[mi][3])
                    : "r"(stoff + aAddr + mi * (16*G_PITCH) + ks * 32));
            }
            uint32_t bf[8][2];
            #pragma unroll
            for (int p = 0; p < 4; ++p) {
                asm volatile("ldmatrix.sync.aligned.m8n8.x4.shared.b16 {%0,%1,%2,%3}, [%4];"
                    : "=r"(bf[p*2][0]), "=r"(bf[p*2][1]), "=r"(bf[p*2+1][0]), "=r"(bf[p*2+1][1])
                    : "r"(stoff + bAddr + p * (16*G_PITCH) + ks * 32));
            }
            #pragma unroll
            for (int mi = 0; mi < 4; ++mi)
                #pragma unroll
                for (int ni = 0; ni < 8; ++ni) {
                    asm volatile(
                        "mma.sync.aligned.m16n8k16.row.col.f32.f16.f16.f32 "
                        "{%0,%1,%2,%3}, {%4,%5,%6,%7}, {%8,%9}, {%0,%1,%2,%3};"
                        : "+f"(c[mi][ni][0]), "+f"(c[mi][ni][1]),
                          "+f"(c[mi][ni][2]), "+f"(c[mi][ni][3])
                        : "r"(af[mi][0]), "r"(af[mi][1]), "r"(af[mi][2]), "r"(af[mi][3]),
                          "r"(bf[ni][0]), "r"(bf[ni][1]));
                }
        }
        if (++stage == 3) stage = 0;
    }

    const int gid = lane >> 2, tig = lane & 3;
    #pragma unroll
    for (int mi = 0; mi < 4; ++mi) {
        #pragma unroll
        for (int ni = 0; ni < 8; ++ni) {
            int row = m0 + wm*64 + mi*16 + gid;
            int col = n0 + wn*64 + ni*8 + tig*2;
            float2 v0 = make_float2(c[mi][ni][0], c[mi][ni][1]);
            float2 v1 = make_float2(c[mi][ni][2], c[mi][ni][3]);
            *reinterpret_cast<float2*>(&g_go[(size_t)row * H_ + col]) = v0;
            *reinterpret_cast<float2*>(&g_go[(size_t)(row + 8) * H_ + col]) = v1;
        }
    }
}

// ============ 5) out = RMSNorm(o)*gw * go * sigmoid(go) ============
__global__ void final_kernel(const float* __restrict__ gw, float* __restrict__ out) {
    const int m = blockIdx.x;
    const int tid = threadIdx.x;
    const float* orow = &g_o[(size_t)m * H_];
    const float* grow = &g_go[(size_t)m * H_];

    float ss = 0.f;
    float4 ov[2];
    #pragma unroll
    for (int t = 0; t < 2; ++t) {
        ov[t] = *reinterpret_cast<const float4*>(&orow[tid * 8 + t * 4]);
        ss += ov[t].x*ov[t].x + ov[t].y*ov[t].y + ov[t].z*ov[t].z + ov[t].w*ov[t].w;
    }
    #pragma unroll
    for (int o = 16; o > 0; o >>= 1)
        ss += __shfl_xor_sync(0xffffffffu, ss, o);
    __shared__ float red[8];
    __shared__ float s_rs;
    if ((tid & 31) == 0) red[tid >> 5] = ss;
    __syncthreads();
    if (tid == 0) {
        float t = 0.f;
        #pragma unroll
        for (int i = 0; i < 8; ++i) t += red[i];
        s_rs = rsqrtf(t * (1.f / H_) + EPS_);
    }
    __syncthreads();
    const float rs = s_rs;

    #pragma unroll
    for (int t = 0; t < 2; ++t) {
        int j = tid * 8 + t * 4;
        float4 g4 = *reinterpret_cast<const float4*>(&grow[j]);
        float4 w4 = *reinterpret_cast<const float4*>(&gw[j]);
        float4 r;
        r.x = ov[t].x * rs * w4.x * g4.x * sigmoid_f(g4.x);
        r.y = ov[t].y * rs * w4.y * g4.y * sigmoid_f(g4.y);
        r.z = ov[t].z * rs * w4.z * g4.z * sigmoid_f(g4.z);
        r.w = ov[t].w * rs * w4.w * g4.w * sigmoid_f(g4.w);
        *reinterpret_cast<float4*>(&out[(size_t)m * H_ + j]) = r;
    }
}

// ---------------------------------------------------------------------
extern "C" void kernel_launch(void* const* d_in, const int* in_sizes, int n_in,
                              void* d_out, int out_size) {
    const float* x   = (const float*)d_in[0];
    const float* Wq  = (const float*)d_in[1];
    const float* Wk  = (const float*)d_in[2];
    const float* Wog = (const float*)d_in[3];
    const float* Wig = (const float*)d_in[4];
    const float* gw  = (const float*)d_in[5];
    float* out = (float*)d_out;

    cudaFuncSetAttribute(proj_tc_kernel, cudaFuncAttributeMaxDynamicSharedMemorySize, P_SMEM);
    cudaFuncSetAttribute(gla_o_tc_kernel, cudaFuncAttributeMaxDynamicSharedMemorySize, O_SMEM);
    cudaFuncSetAttribute(gemm_tc_kernel, cudaFuncAttributeMaxDynamicSharedMemorySize, G_SMEM);

    convX_kernel <<<(BL_*H_/4)/256,  256>>>(x);
    convW_kernel <<<(256*H_/4)/256,  256>>>(Wq, Wk);
    proj_tc_kernel<<<dim3(4, 32),    128, P_SMEM>>>();
    gla_A_kernel <<<dim3(NT_, B_, 4), 256>>>();
    gla_o_tc_kernel<<<dim3(H_/256, NT_, B_), 256, O_SMEM>>>();
    convB_kernel <<<(H_*2*H_/4)/256, 256>>>(Wog, Wig);
    gemm_tc_kernel<<<dim3(H_/256, BL_/128), 256, G_SMEM>>>();
    final_kernel <<<BL_,             256>>>(gw, out);
}